// round 1
// baseline (speedup 1.0000x reference)
#include <cuda_runtime.h>
#include <math.h>

#define T_ 2048
#define DIM_ 2048
#define NH 32
#define HD 64
#define QKVD 6144

// ---------------- scratch (no cudaMalloc allowed) ----------------
__device__ float g_qkv[T_ * QKVD];          // 50.3 MB
__device__ float g_tauq[T_ * NH];
__device__ float g_tauv[T_ * NH];
__device__ float g_Q[NH * T_ * HD];         // 16.8 MB
__device__ float g_K[NH * T_ * HD];
__device__ float g_V[NH * T_ * HD];
__device__ float g_attn[T_ * DIM_];

// ---------------- SGEMM: C[M,N] = A[M,K] @ B[N,K]^T + bias[N] ----------------
// 128x128 block tile, BK=16, 256 threads, 8x8 per-thread fragment.
__global__ __launch_bounds__(256, 2)
void sgemm_bias_kernel(const float* __restrict__ A, const float* __restrict__ B,
                       const float* __restrict__ bias, float* __restrict__ C,
                       int N, int K) {
    __shared__ float As[16][129];
    __shared__ float Bs[16][129];

    const int tid = threadIdx.x;
    const int ty = tid >> 4;
    const int tx = tid & 15;

    const float* Ab = A + (size_t)blockIdx.y * 128 * K;
    const float* Bb = B + (size_t)blockIdx.x * 128 * K;

    float acc[8][8];
#pragma unroll
    for (int i = 0; i < 8; i++)
#pragma unroll
        for (int j = 0; j < 8; j++) acc[i][j] = 0.f;

    for (int k0 = 0; k0 < K; k0 += 16) {
#pragma unroll
        for (int e = tid; e < 512; e += 256) {
            int row = e >> 2;
            int c4 = (e & 3) << 2;
            float4 av = *(const float4*)(Ab + (size_t)row * K + k0 + c4);
            As[c4 + 0][row] = av.x; As[c4 + 1][row] = av.y;
            As[c4 + 2][row] = av.z; As[c4 + 3][row] = av.w;
            float4 bv = *(const float4*)(Bb + (size_t)row * K + k0 + c4);
            Bs[c4 + 0][row] = bv.x; Bs[c4 + 1][row] = bv.y;
            Bs[c4 + 2][row] = bv.z; Bs[c4 + 3][row] = bv.w;
        }
        __syncthreads();

#pragma unroll
        for (int k = 0; k < 16; k++) {
            float a[8], b[8];
#pragma unroll
            for (int i = 0; i < 4; i++) {
                a[i]     = As[k][ty * 4 + i];
                a[i + 4] = As[k][64 + ty * 4 + i];
                b[i]     = Bs[k][tx * 4 + i];
                b[i + 4] = Bs[k][64 + tx * 4 + i];
            }
#pragma unroll
            for (int i = 0; i < 8; i++)
#pragma unroll
                for (int j = 0; j < 8; j++) acc[i][j] += a[i] * b[j];
        }
        __syncthreads();
    }

#pragma unroll
    for (int i = 0; i < 8; i++) {
        int r = blockIdx.y * 128 + ((i < 4) ? (ty * 4 + i) : (64 + ty * 4 + i - 4));
#pragma unroll
        for (int j = 0; j < 8; j++) {
            int c = blockIdx.x * 128 + ((j < 4) ? (tx * 4 + j) : (64 + tx * 4 + j - 4));
            C[(size_t)r * N + c] = acc[i][j] + bias[c];
        }
    }
}

// ---------------- tau projections: tok_q/tok_v = tanh(gelu(qkv) @ tau_w^T) + tau_pos ----------------
// One block per token; 64 fp32 accumulators per thread; warp + smem reduce.
__global__ __launch_bounds__(256)
void tau_kernel(const float* __restrict__ qkv,
                const float* __restrict__ tau_wq, const float* __restrict__ tau_wv,
                const float* __restrict__ tau_alpha, const int* __restrict__ positions,
                float* __restrict__ tauq, float* __restrict__ tauv) {
    const int t = blockIdx.x;
    const int tid = threadIdx.x;
    const int lane = tid & 31;
    const int warp = tid >> 5;

    float accq[32], accv[32];
#pragma unroll
    for (int h = 0; h < 32; h++) { accq[h] = 0.f; accv[h] = 0.f; }

    const float* row = qkv + (size_t)t * QKVD;
    for (int j = tid; j < QKVD; j += 256) {
        float x = row[j];
        float g = 0.5f * x * (1.0f + erff(x * 0.70710678118654752f));
#pragma unroll
        for (int h = 0; h < 32; h++) {
            accq[h] += g * tau_wq[h * QKVD + j];
            accv[h] += g * tau_wv[h * QKVD + j];
        }
    }

    __shared__ float red[64][8];
#pragma unroll
    for (int o = 0; o < 64; o++) {
        float v = (o < 32) ? accq[o] : accv[o - 32];
#pragma unroll
        for (int off = 16; off > 0; off >>= 1)
            v += __shfl_down_sync(0xffffffffu, v, off);
        if (lane == 0) red[o][warp] = v;
    }
    __syncthreads();

    if (tid < 64) {
        float s = 0.f;
#pragma unroll
        for (int w = 0; w < 8; w++) s += red[tid][w];
        int h = tid & 31;
        float pl = logf(fmaxf((float)positions[t] + 1.0f, 1e-6f));
        float tp = 0.5f + 1.0f / (1.0f + expf(-tau_alpha[h] * pl));
        float val = tanhf(s) + tp;
        if (tid < 32) tauq[t * NH + h] = val;
        else          tauv[t * NH + h] = val;
    }
}

// ---------------- prep: tau scaling + NeoX RoPE -> Q/K/V in [H][T][D] ----------------
__global__ __launch_bounds__(256)
void prep_kernel(const float* __restrict__ qkv, const int* __restrict__ positions,
                 const float* __restrict__ tauq, const float* __restrict__ tauv,
                 float* __restrict__ Qo, float* __restrict__ Ko, float* __restrict__ Vo) {
    const int t = blockIdx.x;
    const float p = (float)positions[t];
    const float* row = qkv + (size_t)t * QKVD;

    for (int e = threadIdx.x; e < DIM_; e += 256) {
        int h = e >> 6;
        int d = e & 63;
        float tq = tauq[t * NH + h];
        float tv = tauv[t * NH + h];

        float qo = row[e] * tq;
        float ko = row[DIM_ + e];
        float vo = row[2 * DIM_ + e] * tv;

        if (d < 32) {
            int i = (d < 16) ? d : (d - 16);
            // inv_freq = ROPE_THETA^(-i/16); log2(1e6)/16 = 1.2457230355827609
            float ang = p * exp2f(-(float)i * 1.2457230355827609f);
            float s, c;
            sincosf(ang, &s, &c);
            if (d < 16) {
                float q2 = row[e + 16] * tq;
                float k2 = row[DIM_ + e + 16];
                qo = qo * c - q2 * s;
                ko = ko * c - k2 * s;
            } else {
                float q1 = row[e - 16] * tq;
                float k1 = row[DIM_ + e - 16];
                qo = qo * c + q1 * s;
                ko = ko * c + k1 * s;
            }
        }
        size_t o = (size_t)h * T_ * HD + (size_t)t * HD + d;
        Qo[o] = qo;
        Ko[o] = ko;
        Vo[o] = vo;
    }
}

// ---------------- flash attention: causal, online softmax, 64x64 tiles ----------------
// grid (32 q-tiles, 32 heads), 256 threads, 4x4 fragments, stride-65 smem.
#define FS 65
#define FLASH_SMEM (4 * 64 * FS * 4)
__global__ __launch_bounds__(256)
void flash_kernel(const float* __restrict__ Qg, const float* __restrict__ Kg,
                  const float* __restrict__ Vg, float* __restrict__ attn) {
    extern __shared__ float sm[];
    float* Qs = sm;
    float* Ks = sm + 64 * FS;
    float* Vs = sm + 2 * 64 * FS;
    float* Ps = sm + 3 * 64 * FS;

    const int qt = blockIdx.x;
    const int h = blockIdx.y;
    const int tid = threadIdx.x;
    const int ty = tid >> 4;
    const int tx = tid & 15;

    const float* Qh = Qg + (size_t)h * T_ * HD;
    const float* Kh = Kg + (size_t)h * T_ * HD;
    const float* Vh = Vg + (size_t)h * T_ * HD;

    // load Q tile pre-scaled by D^-0.5
    for (int e = tid; e < 64 * 16; e += 256) {
        int r = e >> 4;
        int c4 = (e & 15) << 2;
        float4 v = *(const float4*)(Qh + (size_t)(qt * 64 + r) * HD + c4);
        Qs[r * FS + c4 + 0] = v.x * 0.125f;
        Qs[r * FS + c4 + 1] = v.y * 0.125f;
        Qs[r * FS + c4 + 2] = v.z * 0.125f;
        Qs[r * FS + c4 + 3] = v.w * 0.125f;
    }

    float m[4], l[4], o[4][4];
#pragma unroll
    for (int i = 0; i < 4; i++) {
        m[i] = -1e30f; l[i] = 0.f;
#pragma unroll
        for (int j = 0; j < 4; j++) o[i][j] = 0.f;
    }

    for (int kt = 0; kt <= qt; kt++) {
        for (int e = tid; e < 64 * 16; e += 256) {
            int r = e >> 4;
            int c4 = (e & 15) << 2;
            float4 kv = *(const float4*)(Kh + (size_t)(kt * 64 + r) * HD + c4);
            Ks[r * FS + c4 + 0] = kv.x; Ks[r * FS + c4 + 1] = kv.y;
            Ks[r * FS + c4 + 2] = kv.z; Ks[r * FS + c4 + 3] = kv.w;
            float4 vv = *(const float4*)(Vh + (size_t)(kt * 64 + r) * HD + c4);
            Vs[r * FS + c4 + 0] = vv.x; Vs[r * FS + c4 + 1] = vv.y;
            Vs[r * FS + c4 + 2] = vv.z; Vs[r * FS + c4 + 3] = vv.w;
        }
        __syncthreads();

        float s[4][4];
#pragma unroll
        for (int i = 0; i < 4; i++)
#pragma unroll
            for (int j = 0; j < 4; j++) s[i][j] = 0.f;

        for (int d = 0; d < 64; d++) {
            float a[4], b[4];
#pragma unroll
            for (int i = 0; i < 4; i++) a[i] = Qs[(ty * 4 + i) * FS + d];
#pragma unroll
            for (int j = 0; j < 4; j++) b[j] = Ks[(tx * 4 + j) * FS + d];
#pragma unroll
            for (int i = 0; i < 4; i++)
#pragma unroll
                for (int j = 0; j < 4; j++) s[i][j] += a[i] * b[j];
        }

        if (kt == qt) {
#pragma unroll
            for (int i = 0; i < 4; i++) {
                int qi = ty * 4 + i;
#pragma unroll
                for (int j = 0; j < 4; j++) {
                    int kj = tx * 4 + j;
                    if (kj > qi) s[i][j] = -1e30f;
                }
            }
        }

#pragma unroll
        for (int i = 0; i < 4; i++) {
            float rm = fmaxf(fmaxf(s[i][0], s[i][1]), fmaxf(s[i][2], s[i][3]));
#pragma unroll
            for (int off = 8; off > 0; off >>= 1)
                rm = fmaxf(rm, __shfl_xor_sync(0xffffffffu, rm, off));
            float mn = fmaxf(m[i], rm);
            float alpha = __expf(m[i] - mn);
            float rs = 0.f;
#pragma unroll
            for (int j = 0; j < 4; j++) {
                s[i][j] = __expf(s[i][j] - mn);
                rs += s[i][j];
            }
#pragma unroll
            for (int off = 8; off > 0; off >>= 1)
                rs += __shfl_xor_sync(0xffffffffu, rs, off);
            l[i] = l[i] * alpha + rs;
            m[i] = mn;
#pragma unroll
            for (int j = 0; j < 4; j++) o[i][j] *= alpha;
#pragma unroll
            for (int j = 0; j < 4; j++)
                Ps[(ty * 4 + i) * FS + tx * 4 + j] = s[i][j];
        }
        __syncthreads();

        for (int c = 0; c < 64; c++) {
            float pa[4], vb[4];
#pragma unroll
            for (int i = 0; i < 4; i++) pa[i] = Ps[(ty * 4 + i) * FS + c];
#pragma unroll
            for (int j = 0; j < 4; j++) vb[j] = Vs[c * FS + tx * 4 + j];
#pragma unroll
            for (int i = 0; i < 4; i++)
#pragma unroll
                for (int j = 0; j < 4; j++) o[i][j] += pa[i] * vb[j];
        }
        __syncthreads();
    }

#pragma unroll
    for (int i = 0; i < 4; i++) {
        float inv = 1.0f / l[i];
        int t = qt * 64 + ty * 4 + i;
#pragma unroll
        for (int j = 0; j < 4; j++) {
            attn[(size_t)t * DIM_ + h * 64 + tx * 4 + j] = o[i][j] * inv;
        }
    }
}

// ---------------- launch ----------------
extern "C" void kernel_launch(void* const* d_in, const int* in_sizes, int n_in,
                              void* d_out, int out_size) {
    const int*   positions = (const int*)d_in[0];
    const float* hidden    = (const float*)d_in[1];
    const float* Wqkv      = (const float*)d_in[2];
    const float* bqkv      = (const float*)d_in[3];
    const float* Wout      = (const float*)d_in[4];
    const float* bout      = (const float*)d_in[5];
    const float* tau_alpha = (const float*)d_in[6];
    const float* tau_wq    = (const float*)d_in[7];
    const float* tau_wv    = (const float*)d_in[8];
    float* out = (float*)d_out;

    float *qkv, *tauq, *tauv, *Q, *K, *V, *attn;
    cudaGetSymbolAddress((void**)&qkv,  g_qkv);
    cudaGetSymbolAddress((void**)&tauq, g_tauq);
    cudaGetSymbolAddress((void**)&tauv, g_tauv);
    cudaGetSymbolAddress((void**)&Q,    g_Q);
    cudaGetSymbolAddress((void**)&K,    g_K);
    cudaGetSymbolAddress((void**)&V,    g_V);
    cudaGetSymbolAddress((void**)&attn, g_attn);

    cudaFuncSetAttribute(flash_kernel,
                         cudaFuncAttributeMaxDynamicSharedMemorySize, FLASH_SMEM);

    // 1. qkv = hidden @ Wqkv^T + bqkv
    sgemm_bias_kernel<<<dim3(QKVD / 128, T_ / 128), 256>>>(hidden, Wqkv, bqkv, qkv, QKVD, DIM_);
    // 2. tau projections
    tau_kernel<<<T_, 256>>>(qkv, tau_wq, tau_wv, tau_alpha, positions, tauq, tauv);
    // 3. scale + rope -> Q,K,V [H][T][D]
    prep_kernel<<<T_, 256>>>(qkv, positions, tauq, tauv, Q, K, V);
    // 4. causal flash attention
    flash_kernel<<<dim3(T_ / 64, NH), 256, FLASH_SMEM>>>(Q, K, V, attn);
    // 5. out = attn @ Wout^T + bout
    sgemm_bias_kernel<<<dim3(DIM_ / 128, T_ / 128), 256>>>(attn, Wout, bout, out, DIM_, DIM_);
}

// round 3
// speedup vs baseline: 1.6088x; 1.6088x over previous
#include <cuda_runtime.h>
#include <cuda_bf16.h>
#include <math.h>
#include <stdint.h>

#define T_ 2048
#define DIM_ 2048
#define NH 32
#define HD 64
#define QKVD 6144

// ---------------- scratch (no cudaMalloc allowed) ----------------
__device__ float g_qkv[T_ * QKVD];
__device__ float g_tauq[T_ * NH];
__device__ float g_tauv[T_ * NH];
__device__ float g_Q[NH * T_ * HD];
__device__ float g_K[NH * T_ * HD];
__device__ float g_V[NH * T_ * HD];
__device__ float g_attn[T_ * DIM_];
__device__ float g_taupart[16 * T_ * 64];
__device__ __nv_bfloat16 g_Ahi[T_ * DIM_];
__device__ __nv_bfloat16 g_Alo[T_ * DIM_];
__device__ __nv_bfloat16 g_Whi[QKVD * DIM_];
__device__ __nv_bfloat16 g_Wlo[QKVD * DIM_];

// ================= helpers =================
__device__ __forceinline__ uint32_t smem_u32(const void* p) {
    uint32_t a;
    asm("{ .reg .u64 t; cvta.to.shared.u64 t, %1; cvt.u32.u64 %0, t; }" : "=r"(a) : "l"(p));
    return a;
}

__device__ __forceinline__ void ldsm4(uint32_t* r, uint32_t addr) {
    asm volatile("ldmatrix.sync.aligned.m8n8.x4.shared.b16 {%0,%1,%2,%3}, [%4];"
        : "=r"(r[0]), "=r"(r[1]), "=r"(r[2]), "=r"(r[3]) : "r"(addr));
}

__device__ __forceinline__ void mma16816(float* d, const uint32_t* a, const uint32_t* b) {
    asm volatile("mma.sync.aligned.m16n8k16.row.col.f32.bf16.bf16.f32 "
        "{%0,%1,%2,%3}, {%4,%5,%6,%7}, {%8,%9}, {%0,%1,%2,%3};"
        : "+f"(d[0]), "+f"(d[1]), "+f"(d[2]), "+f"(d[3])
        : "r"(a[0]), "r"(a[1]), "r"(a[2]), "r"(a[3]), "r"(b[0]), "r"(b[1]));
}

__device__ __forceinline__ void cp_async16(uint32_t dst, const void* src) {
    asm volatile("cp.async.cg.shared.global [%0], [%1], 16;" :: "r"(dst), "l"(src) : "memory");
}
#define CP_COMMIT() asm volatile("cp.async.commit_group;" ::: "memory")
#define CP_WAIT(n)  asm volatile("cp.async.wait_group %0;" :: "n"(n) : "memory")

// ================= split-bf16 decomposition =================
__global__ __launch_bounds__(256)
void decomp_kernel(const float* __restrict__ in, __nv_bfloat16* __restrict__ hi,
                   __nv_bfloat16* __restrict__ lo, int n4) {
    int i = blockIdx.x * 256 + threadIdx.x;
    if (i >= n4) return;
    float4 v = ((const float4*)in)[i];
    __nv_bfloat16 h0 = __float2bfloat16_rn(v.x);
    __nv_bfloat16 h1 = __float2bfloat16_rn(v.y);
    __nv_bfloat16 h2 = __float2bfloat16_rn(v.z);
    __nv_bfloat16 h3 = __float2bfloat16_rn(v.w);
    __nv_bfloat16 l0 = __float2bfloat16_rn(v.x - __bfloat162float(h0));
    __nv_bfloat16 l1 = __float2bfloat16_rn(v.y - __bfloat162float(h1));
    __nv_bfloat16 l2 = __float2bfloat16_rn(v.z - __bfloat162float(h2));
    __nv_bfloat16 l3 = __float2bfloat16_rn(v.w - __bfloat162float(h3));
    ((__nv_bfloat162*)hi)[i * 2 + 0] = __halves2bfloat162(h0, h1);
    ((__nv_bfloat162*)hi)[i * 2 + 1] = __halves2bfloat162(h2, h3);
    ((__nv_bfloat162*)lo)[i * 2 + 0] = __halves2bfloat162(l0, l1);
    ((__nv_bfloat162*)lo)[i * 2 + 1] = __halves2bfloat162(l2, l3);
}

// ================= HMMA split-bf16 GEMM =================
// C[M,N] = A[M,K] @ B[N,K]^T + bias[N]
// Tile 128x128, BK=32, 3-stage cp.async pipeline, 8 warps (4x2).
// Smem rows padded to 80B (32 bf16 -> 40 slots) for conflict-free ldmatrix.
#define MAT_BYTES  (128 * 80)
#define STAGE_BYTES (4 * MAT_BYTES)
#define GSMEM (3 * STAGE_BYTES)

__global__ __launch_bounds__(256)
void gemm_hmma_kernel(const __nv_bfloat16* __restrict__ Ahi, const __nv_bfloat16* __restrict__ Alo,
                      const __nv_bfloat16* __restrict__ Bhi, const __nv_bfloat16* __restrict__ Blo,
                      const float* __restrict__ bias, float* __restrict__ C,
                      int N, int K) {
    extern __shared__ char smem[];
    const uint32_t sbase = smem_u32(smem);
    const int tid = threadIdx.x;
    const int wid = tid >> 5;
    const int lane = tid & 31;
    const int wm = wid >> 1;        // 0..3
    const int wn = wid & 1;         // 0..1
    const int bx = blockIdx.x, by = blockIdx.y;
    const int nch = K / 32;

    // per-thread load slots: 512 chunks of 16B per matrix, 2 per thread
    const int lrow0 = tid >> 2;            // 0..63
    const int lc0 = tid & 3;

    float acc[2][8][4];
#pragma unroll
    for (int mt = 0; mt < 2; mt++)
#pragma unroll
        for (int nt = 0; nt < 8; nt++)
#pragma unroll
            for (int r = 0; r < 4; r++) acc[mt][nt][r] = 0.f;

    // ---- load one stage ----
    auto load_stage = [&](int s, int ci) {
        uint32_t st = sbase + s * STAGE_BYTES;
        int k0 = ci * 32;
#pragma unroll
        for (int it = 0; it < 2; it++) {
            int row = lrow0 + it * 64;
            uint32_t so = (uint32_t)row * 80 + lc0 * 16;
            size_t ga = ((size_t)(by * 128 + row) * K + k0 + lc0 * 8);
            size_t gb = ((size_t)(bx * 128 + row) * K + k0 + lc0 * 8);
            cp_async16(st + so,                 Ahi + ga);
            cp_async16(st + MAT_BYTES + so,     Alo + ga);
            cp_async16(st + 2 * MAT_BYTES + so, Bhi + gb);
            cp_async16(st + 3 * MAT_BYTES + so, Blo + gb);
        }
        CP_COMMIT();
    };

    load_stage(0, 0);
    if (nch > 1) load_stage(1, 1);

    for (int ci = 0; ci < nch; ci++) {
        if (ci == nch - 1) { CP_WAIT(0); } else { CP_WAIT(1); }
        __syncthreads();

        if (ci + 2 < nch) load_stage((ci + 2) % 3, ci + 2);

        uint32_t st = sbase + (ci % 3) * STAGE_BYTES;
        uint32_t aHi = st, aLo = st + MAT_BYTES;
        uint32_t bHi = st + 2 * MAT_BYTES, bLo = st + 3 * MAT_BYTES;

#pragma unroll
        for (int ks = 0; ks < 2; ks++) {
            uint32_t ah[2][4], al[2][4];
            uint32_t aoff = (uint32_t)(wm * 32 + (lane & 15)) * 80 + ks * 32 + (lane >> 4) * 16;
#pragma unroll
            for (int mt = 0; mt < 2; mt++) {
                ldsm4(ah[mt], aHi + aoff + mt * 16 * 80);
                ldsm4(al[mt], aLo + aoff + mt * 16 * 80);
            }
            int g = lane >> 3;
#pragma unroll
            for (int half = 0; half < 2; half++) {
                uint32_t bh[2][4], bl[2][4];
#pragma unroll
                for (int p = 0; p < 2; p++) {
                    int row = wn * 64 + half * 32 + p * 16 + (g >> 1) * 8 + (lane & 7);
                    uint32_t boff = (uint32_t)row * 80 + ks * 32 + (g & 1) * 16;
                    ldsm4(bh[p], bHi + boff);
                    ldsm4(bl[p], bLo + boff);
                }
#pragma unroll
                for (int mt = 0; mt < 2; mt++)
#pragma unroll
                    for (int p = 0; p < 2; p++)
#pragma unroll
                        for (int pt = 0; pt < 2; pt++) {
                            int nt = half * 4 + p * 2 + pt;
                            mma16816(acc[mt][nt], ah[mt], &bh[p][pt * 2]);
                            mma16816(acc[mt][nt], al[mt], &bh[p][pt * 2]);
                            mma16816(acc[mt][nt], ah[mt], &bl[p][pt * 2]);
                        }
            }
        }
        __syncthreads();
    }

    // ---- epilogue: direct stores + bias ----
#pragma unroll
    for (int mt = 0; mt < 2; mt++) {
        int r0 = by * 128 + wm * 32 + mt * 16 + (lane >> 2);
#pragma unroll
        for (int nt = 0; nt < 8; nt++) {
            int c0 = bx * 128 + wn * 64 + nt * 8 + (lane & 3) * 2;
            float b0 = bias[c0], b1 = bias[c0 + 1];
            C[(size_t)r0 * N + c0]           = acc[mt][nt][0] + b0;
            C[(size_t)r0 * N + c0 + 1]       = acc[mt][nt][1] + b1;
            C[(size_t)(r0 + 8) * N + c0]     = acc[mt][nt][2] + b0;
            C[(size_t)(r0 + 8) * N + c0 + 1] = acc[mt][nt][3] + b1;
        }
    }
}

// ================= tau: split-K tiled GEMM over gelu(qkv) =================
__global__ __launch_bounds__(256)
void tau_gemm_kernel(const float* __restrict__ qkv, const float* __restrict__ wq,
                     const float* __restrict__ wv, float* __restrict__ part) {
    __shared__ float sA[32][129];
    __shared__ float sW[32][65];
    const int tid = threadIdx.x;
    const int t0 = blockIdx.x * 128;
    const int k0 = blockIdx.y * 384;
    const int ty = tid >> 4, tx = tid & 15;

    float acc[8][4];
#pragma unroll
    for (int i = 0; i < 8; i++)
#pragma unroll
        for (int j = 0; j < 4; j++) acc[i][j] = 0.f;

    for (int kt = 0; kt < 12; kt++) {
        int kb = k0 + kt * 32;
        for (int e = tid; e < 4096; e += 256) {
            int tok = e >> 5, k = e & 31;
            float x = qkv[(size_t)(t0 + tok) * QKVD + kb + k];
            sA[k][tok] = 0.5f * x * (1.0f + erff(x * 0.70710678118654752f));
        }
        for (int e = tid; e < 2048; e += 256) {
            int n = e >> 5, k = e & 31;
            const float* w = (n < 32) ? (wq + (size_t)n * QKVD) : (wv + (size_t)(n - 32) * QKVD);
            sW[k][n] = w[kb + k];
        }
        __syncthreads();
#pragma unroll
        for (int k = 0; k < 32; k++) {
            float a[8], b[4];
#pragma unroll
            for (int i = 0; i < 8; i++) a[i] = sA[k][ty * 8 + i];
#pragma unroll
            for (int j = 0; j < 4; j++) b[j] = sW[k][tx * 4 + j];
#pragma unroll
            for (int i = 0; i < 8; i++)
#pragma unroll
                for (int j = 0; j < 4; j++) acc[i][j] += a[i] * b[j];
        }
        __syncthreads();
    }
#pragma unroll
    for (int i = 0; i < 8; i++)
#pragma unroll
        for (int j = 0; j < 4; j++)
            part[((size_t)blockIdx.y * T_ + t0 + ty * 8 + i) * 64 + tx * 4 + j] = acc[i][j];
}

__global__ __launch_bounds__(256)
void tau_finish_kernel(const float* __restrict__ part, const float* __restrict__ alpha,
                       const int* __restrict__ positions,
                       float* __restrict__ tauq, float* __restrict__ tauv) {
    int idx = blockIdx.x * 256 + threadIdx.x;
    if (idx >= T_ * 64) return;
    int t = idx >> 6, o = idx & 63;
    float s = 0.f;
#pragma unroll
    for (int ks = 0; ks < 16; ks++) s += part[(size_t)ks * T_ * 64 + idx];
    int h = o & 31;
    float pl = logf(fmaxf((float)positions[t] + 1.0f, 1e-6f));
    float tp = 0.5f + 1.0f / (1.0f + expf(-alpha[h] * pl));
    float v = tanhf(s) + tp;
    if (o < 32) tauq[t * NH + h] = v;
    else        tauv[t * NH + h] = v;
}

// ================= prep: tau scaling + NeoX RoPE -> Q/K/V [H][T][D] =================
__global__ __launch_bounds__(256)
void prep_kernel(const float* __restrict__ qkv, const int* __restrict__ positions,
                 const float* __restrict__ tauq, const float* __restrict__ tauv,
                 float* __restrict__ Qo, float* __restrict__ Ko, float* __restrict__ Vo) {
    const int t = blockIdx.x;
    const float p = (float)positions[t];
    const float* row = qkv + (size_t)t * QKVD;

    for (int e = threadIdx.x; e < DIM_; e += 256) {
        int h = e >> 6;
        int d = e & 63;
        float tq = tauq[t * NH + h];
        float tv = tauv[t * NH + h];

        float qo = row[e] * tq;
        float ko = row[DIM_ + e];
        float vo = row[2 * DIM_ + e] * tv;

        if (d < 32) {
            int i = (d < 16) ? d : (d - 16);
            float ang = p * exp2f(-(float)i * 1.2457230355827609f);
            float s, c;
            sincosf(ang, &s, &c);
            if (d < 16) {
                float q2 = row[e + 16] * tq;
                float k2 = row[DIM_ + e + 16];
                qo = qo * c - q2 * s;
                ko = ko * c - k2 * s;
            } else {
                float q1 = row[e - 16] * tq;
                float k1 = row[DIM_ + e - 16];
                qo = qo * c + q1 * s;
                ko = ko * c + k1 * s;
            }
        }
        size_t o = (size_t)h * T_ * HD + (size_t)t * HD + d;
        Qo[o] = qo;
        Ko[o] = ko;
        Vo[o] = vo;
    }
}

// ================= flash attention (fp32, unchanged) =================
#define FS 65
#define FLASH_SMEM (4 * 64 * FS * 4)
__global__ __launch_bounds__(256)
void flash_kernel(const float* __restrict__ Qg, const float* __restrict__ Kg,
                  const float* __restrict__ Vg, float* __restrict__ attn) {
    extern __shared__ float sm[];
    float* Qs = sm;
    float* Ks = sm + 64 * FS;
    float* Vs = sm + 2 * 64 * FS;
    float* Ps = sm + 3 * 64 * FS;

    const int qt = blockIdx.x;
    const int h = blockIdx.y;
    const int tid = threadIdx.x;
    const int ty = tid >> 4;
    const int tx = tid & 15;

    const float* Qh = Qg + (size_t)h * T_ * HD;
    const float* Kh = Kg + (size_t)h * T_ * HD;
    const float* Vh = Vg + (size_t)h * T_ * HD;

    for (int e = tid; e < 64 * 16; e += 256) {
        int r = e >> 4;
        int c4 = (e & 15) << 2;
        float4 v = *(const float4*)(Qh + (size_t)(qt * 64 + r) * HD + c4);
        Qs[r * FS + c4 + 0] = v.x * 0.125f;
        Qs[r * FS + c4 + 1] = v.y * 0.125f;
        Qs[r * FS + c4 + 2] = v.z * 0.125f;
        Qs[r * FS + c4 + 3] = v.w * 0.125f;
    }

    float m[4], l[4], o[4][4];
#pragma unroll
    for (int i = 0; i < 4; i++) {
        m[i] = -1e30f; l[i] = 0.f;
#pragma unroll
        for (int j = 0; j < 4; j++) o[i][j] = 0.f;
    }

    for (int kt = 0; kt <= qt; kt++) {
        for (int e = tid; e < 64 * 16; e += 256) {
            int r = e >> 4;
            int c4 = (e & 15) << 2;
            float4 kv = *(const float4*)(Kh + (size_t)(kt * 64 + r) * HD + c4);
            Ks[r * FS + c4 + 0] = kv.x; Ks[r * FS + c4 + 1] = kv.y;
            Ks[r * FS + c4 + 2] = kv.z; Ks[r * FS + c4 + 3] = kv.w;
            float4 vv = *(const float4*)(Vh + (size_t)(kt * 64 + r) * HD + c4);
            Vs[r * FS + c4 + 0] = vv.x; Vs[r * FS + c4 + 1] = vv.y;
            Vs[r * FS + c4 + 2] = vv.z; Vs[r * FS + c4 + 3] = vv.w;
        }
        __syncthreads();

        float s[4][4];
#pragma unroll
        for (int i = 0; i < 4; i++)
#pragma unroll
            for (int j = 0; j < 4; j++) s[i][j] = 0.f;

        for (int d = 0; d < 64; d++) {
            float a[4], b[4];
#pragma unroll
            for (int i = 0; i < 4; i++) a[i] = Qs[(ty * 4 + i) * FS + d];
#pragma unroll
            for (int j = 0; j < 4; j++) b[j] = Ks[(tx * 4 + j) * FS + d];
#pragma unroll
            for (int i = 0; i < 4; i++)
#pragma unroll
                for (int j = 0; j < 4; j++) s[i][j] += a[i] * b[j];
        }

        if (kt == qt) {
#pragma unroll
            for (int i = 0; i < 4; i++) {
                int qi = ty * 4 + i;
#pragma unroll
                for (int j = 0; j < 4; j++) {
                    int kj = tx * 4 + j;
                    if (kj > qi) s[i][j] = -1e30f;
                }
            }
        }

#pragma unroll
        for (int i = 0; i < 4; i++) {
            float rm = fmaxf(fmaxf(s[i][0], s[i][1]), fmaxf(s[i][2], s[i][3]));
#pragma unroll
            for (int off = 8; off > 0; off >>= 1)
                rm = fmaxf(rm, __shfl_xor_sync(0xffffffffu, rm, off));
            float mn = fmaxf(m[i], rm);
            float alpha = __expf(m[i] - mn);
            float rs = 0.f;
#pragma unroll
            for (int j = 0; j < 4; j++) {
                s[i][j] = __expf(s[i][j] - mn);
                rs += s[i][j];
            }
#pragma unroll
            for (int off = 8; off > 0; off >>= 1)
                rs += __shfl_xor_sync(0xffffffffu, rs, off);
            l[i] = l[i] * alpha + rs;
            m[i] = mn;
#pragma unroll
            for (int j = 0; j < 4; j++) o[i][j] *= alpha;
#pragma unroll
            for (int j = 0; j < 4; j++)
                Ps[(ty * 4 + i) * FS + tx * 4 + j] = s[i][j];
        }
        __syncthreads();

        for (int c = 0; c < 64; c++) {
            float pa[4], vb[4];
#pragma unroll
            for (int i = 0; i < 4; i++) pa[i] = Ps[(ty * 4 + i) * FS + c];
#pragma unroll
            for (int j = 0; j < 4; j++) vb[j] = Vs[c * FS + tx * 4 + j];
#pragma unroll
            for (int i = 0; i < 4; i++)
#pragma unroll
                for (int j = 0; j < 4; j++) o[i][j] += pa[i] * vb[j];
        }
        __syncthreads();
    }

#pragma unroll
    for (int i = 0; i < 4; i++) {
        float inv = 1.0f / l[i];
        int t = qt * 64 + ty * 4 + i;
#pragma unroll
        for (int j = 0; j < 4; j++) {
            attn[(size_t)t * DIM_ + h * 64 + tx * 4 + j] = o[i][j] * inv;
        }
    }
}

// ================= host launch =================
extern "C" void kernel_launch(void* const* d_in, const int* in_sizes, int n_in,
                              void* d_out, int out_size) {
    const int*   positions = (const int*)d_in[0];
    const float* hidden    = (const float*)d_in[1];
    const float* Wqkv      = (const float*)d_in[2];
    const float* bqkv      = (const float*)d_in[3];
    const float* Wout      = (const float*)d_in[4];
    const float* bout      = (const float*)d_in[5];
    const float* tau_alpha = (const float*)d_in[6];
    const float* tau_wq    = (const float*)d_in[7];
    const float* tau_wv    = (const float*)d_in[8];
    float* out = (float*)d_out;

    float *qkv, *tauq, *tauv, *Q, *K, *V, *attn, *taupart;
    __nv_bfloat16 *Ahi, *Alo, *Whi, *Wlo;
    cudaGetSymbolAddress((void**)&qkv,     g_qkv);
    cudaGetSymbolAddress((void**)&tauq,    g_tauq);
    cudaGetSymbolAddress((void**)&tauv,    g_tauv);
    cudaGetSymbolAddress((void**)&Q,       g_Q);
    cudaGetSymbolAddress((void**)&K,       g_K);
    cudaGetSymbolAddress((void**)&V,       g_V);
    cudaGetSymbolAddress((void**)&attn,    g_attn);
    cudaGetSymbolAddress((void**)&taupart, g_taupart);
    cudaGetSymbolAddress((void**)&Ahi,     g_Ahi);
    cudaGetSymbolAddress((void**)&Alo,     g_Alo);
    cudaGetSymbolAddress((void**)&Whi,     g_Whi);
    cudaGetSymbolAddress((void**)&Wlo,     g_Wlo);

    cudaFuncSetAttribute(flash_kernel, cudaFuncAttributeMaxDynamicSharedMemorySize, FLASH_SMEM);
    cudaFuncSetAttribute(gemm_hmma_kernel, cudaFuncAttributeMaxDynamicSharedMemorySize, GSMEM);

    // 1. decompose hidden + Wqkv into bf16 hi/lo planes
    decomp_kernel<<<(T_ * DIM_ / 4 + 255) / 256, 256>>>(hidden, Ahi, Alo, T_ * DIM_ / 4);
    decomp_kernel<<<(QKVD * DIM_ / 4 + 255) / 256, 256>>>(Wqkv, Whi, Wlo, QKVD * DIM_ / 4);
    // 2. qkv = hidden @ Wqkv^T + bqkv (HMMA tensor cores, 3-term split)
    gemm_hmma_kernel<<<dim3(QKVD / 128, T_ / 128), 256, GSMEM>>>(
        Ahi, Alo, Whi, Wlo, bqkv, qkv, QKVD, DIM_);
    // 3. tau projections
    tau_gemm_kernel<<<dim3(T_ / 128, 16), 256>>>(qkv, tau_wq, tau_wv, taupart);
    tau_finish_kernel<<<(T_ * 64 + 255) / 256, 256>>>(taupart, tau_alpha, positions, tauq, tauv);
    // 4. scale + rope -> Q,K,V [H][T][D]
    prep_kernel<<<T_, 256>>>(qkv, positions, tauq, tauv, Q, K, V);
    // 5. causal flash attention
    flash_kernel<<<dim3(T_ / 64, NH), 256, FLASH_SMEM>>>(Q, K, V, attn);
    // 6. out = attn @ Wout^T + bout
    decomp_kernel<<<(T_ * DIM_ / 4 + 255) / 256, 256>>>(attn, Ahi, Alo, T_ * DIM_ / 4);
    decomp_kernel<<<(DIM_ * DIM_ / 4 + 255) / 256, 256>>>(Wout, Whi, Wlo, DIM_ * DIM_ / 4);
    gemm_hmma_kernel<<<dim3(DIM_ / 128, T_ / 128), 256, GSMEM>>>(
        Ahi, Alo, Whi, Wlo, bout, out, DIM_, DIM_);
}

// round 4
// speedup vs baseline: 1.7311x; 1.0760x over previous
#include <cuda_runtime.h>
#include <cuda_bf16.h>
#include <math.h>
#include <stdint.h>

#define T_ 2048
#define DIM_ 2048
#define NH 32
#define HD 64
#define QKVD 6144

// ---------------- scratch ----------------
__device__ float g_qkv[T_ * QKVD];
__device__ float g_tauq[T_ * NH];
__device__ float g_tauv[T_ * NH];
__device__ float g_taupart[32 * T_ * 64];
__device__ __nv_bfloat16 g_Ahi[T_ * DIM_];
__device__ __nv_bfloat16 g_Alo[T_ * DIM_];
__device__ __nv_bfloat16 g_Whi[QKVD * DIM_];
__device__ __nv_bfloat16 g_Wlo[QKVD * DIM_];
__device__ __nv_bfloat16 g_Qhi[NH * T_ * HD];
__device__ __nv_bfloat16 g_Qlo[NH * T_ * HD];
__device__ __nv_bfloat16 g_Khi[NH * T_ * HD];
__device__ __nv_bfloat16 g_Klo[NH * T_ * HD];
__device__ __nv_bfloat16 g_Vhi[NH * T_ * HD];
__device__ __nv_bfloat16 g_Vlo[NH * T_ * HD];

// ================= helpers =================
__device__ __forceinline__ uint32_t smem_u32(const void* p) {
    uint32_t a;
    asm("{ .reg .u64 t; cvta.to.shared.u64 t, %1; cvt.u32.u64 %0, t; }" : "=r"(a) : "l"(p));
    return a;
}
__device__ __forceinline__ void ldsm4(uint32_t* r, uint32_t addr) {
    asm volatile("ldmatrix.sync.aligned.m8n8.x4.shared.b16 {%0,%1,%2,%3}, [%4];"
        : "=r"(r[0]), "=r"(r[1]), "=r"(r[2]), "=r"(r[3]) : "r"(addr));
}
__device__ __forceinline__ void ldsm4t(uint32_t* r, uint32_t addr) {
    asm volatile("ldmatrix.sync.aligned.m8n8.x4.trans.shared.b16 {%0,%1,%2,%3}, [%4];"
        : "=r"(r[0]), "=r"(r[1]), "=r"(r[2]), "=r"(r[3]) : "r"(addr));
}
__device__ __forceinline__ void mma16816(float* d, const uint32_t* a, const uint32_t* b) {
    asm volatile("mma.sync.aligned.m16n8k16.row.col.f32.bf16.bf16.f32 "
        "{%0,%1,%2,%3}, {%4,%5,%6,%7}, {%8,%9}, {%0,%1,%2,%3};"
        : "+f"(d[0]), "+f"(d[1]), "+f"(d[2]), "+f"(d[3])
        : "r"(a[0]), "r"(a[1]), "r"(a[2]), "r"(a[3]), "r"(b[0]), "r"(b[1]));
}
__device__ __forceinline__ void cp_async16(uint32_t dst, const void* src) {
    asm volatile("cp.async.cg.shared.global [%0], [%1], 16;" :: "r"(dst), "l"(src) : "memory");
}
#define CP_COMMIT() asm volatile("cp.async.commit_group;" ::: "memory")
#define CP_WAIT(n)  asm volatile("cp.async.wait_group %0;" :: "n"(n) : "memory")

__device__ __forceinline__ uint32_t pack_bf2(float lo, float hi) {
    __nv_bfloat162 t = __floats2bfloat162_rn(lo, hi);
    return *reinterpret_cast<uint32_t*>(&t);
}

// ================= split-bf16 decomposition =================
__global__ __launch_bounds__(256)
void decomp_kernel(const float* __restrict__ in, __nv_bfloat16* __restrict__ hi,
                   __nv_bfloat16* __restrict__ lo, int n4) {
    int i = blockIdx.x * 256 + threadIdx.x;
    if (i >= n4) return;
    float4 v = ((const float4*)in)[i];
    __nv_bfloat16 h0 = __float2bfloat16_rn(v.x);
    __nv_bfloat16 h1 = __float2bfloat16_rn(v.y);
    __nv_bfloat16 h2 = __float2bfloat16_rn(v.z);
    __nv_bfloat16 h3 = __float2bfloat16_rn(v.w);
    __nv_bfloat16 l0 = __float2bfloat16_rn(v.x - __bfloat162float(h0));
    __nv_bfloat16 l1 = __float2bfloat16_rn(v.y - __bfloat162float(h1));
    __nv_bfloat16 l2 = __float2bfloat16_rn(v.z - __bfloat162float(h2));
    __nv_bfloat16 l3 = __float2bfloat16_rn(v.w - __bfloat162float(h3));
    ((__nv_bfloat162*)hi)[i * 2 + 0] = __halves2bfloat162(h0, h1);
    ((__nv_bfloat162*)hi)[i * 2 + 1] = __halves2bfloat162(h2, h3);
    ((__nv_bfloat162*)lo)[i * 2 + 0] = __halves2bfloat162(l0, l1);
    ((__nv_bfloat162*)lo)[i * 2 + 1] = __halves2bfloat162(l2, l3);
}

// ================= HMMA split-bf16 GEMM (unchanged from R3) =================
#define MAT_BYTES  (128 * 80)
#define STAGE_BYTES (4 * MAT_BYTES)
#define GSMEM (3 * STAGE_BYTES)

__global__ __launch_bounds__(256)
void gemm_hmma_kernel(const __nv_bfloat16* __restrict__ Ahi, const __nv_bfloat16* __restrict__ Alo,
                      const __nv_bfloat16* __restrict__ Bhi, const __nv_bfloat16* __restrict__ Blo,
                      const float* __restrict__ bias, float* __restrict__ C,
                      int N, int K) {
    extern __shared__ char smem[];
    const uint32_t sbase = smem_u32(smem);
    const int tid = threadIdx.x;
    const int wid = tid >> 5;
    const int lane = tid & 31;
    const int wm = wid >> 1;
    const int wn = wid & 1;
    const int bx = blockIdx.x, by = blockIdx.y;
    const int nch = K / 32;

    const int lrow0 = tid >> 2;
    const int lc0 = tid & 3;

    float acc[2][8][4];
#pragma unroll
    for (int mt = 0; mt < 2; mt++)
#pragma unroll
        for (int nt = 0; nt < 8; nt++)
#pragma unroll
            for (int r = 0; r < 4; r++) acc[mt][nt][r] = 0.f;

    auto load_stage = [&](int s, int ci) {
        uint32_t st = sbase + s * STAGE_BYTES;
        int k0 = ci * 32;
#pragma unroll
        for (int it = 0; it < 2; it++) {
            int row = lrow0 + it * 64;
            uint32_t so = (uint32_t)row * 80 + lc0 * 16;
            size_t ga = ((size_t)(by * 128 + row) * K + k0 + lc0 * 8);
            size_t gb = ((size_t)(bx * 128 + row) * K + k0 + lc0 * 8);
            cp_async16(st + so,                 Ahi + ga);
            cp_async16(st + MAT_BYTES + so,     Alo + ga);
            cp_async16(st + 2 * MAT_BYTES + so, Bhi + gb);
            cp_async16(st + 3 * MAT_BYTES + so, Blo + gb);
        }
        CP_COMMIT();
    };

    load_stage(0, 0);
    if (nch > 1) load_stage(1, 1);

    for (int ci = 0; ci < nch; ci++) {
        if (ci == nch - 1) { CP_WAIT(0); } else { CP_WAIT(1); }
        __syncthreads();

        if (ci + 2 < nch) load_stage((ci + 2) % 3, ci + 2);

        uint32_t st = sbase + (ci % 3) * STAGE_BYTES;
        uint32_t aHi = st, aLo = st + MAT_BYTES;
        uint32_t bHi = st + 2 * MAT_BYTES, bLo = st + 3 * MAT_BYTES;

#pragma unroll
        for (int ks = 0; ks < 2; ks++) {
            uint32_t ah[2][4], al[2][4];
            uint32_t aoff = (uint32_t)(wm * 32 + (lane & 15)) * 80 + ks * 32 + (lane >> 4) * 16;
#pragma unroll
            for (int mt = 0; mt < 2; mt++) {
                ldsm4(ah[mt], aHi + aoff + mt * 16 * 80);
                ldsm4(al[mt], aLo + aoff + mt * 16 * 80);
            }
            int g = lane >> 3;
#pragma unroll
            for (int half = 0; half < 2; half++) {
                uint32_t bh[2][4], bl[2][4];
#pragma unroll
                for (int p = 0; p < 2; p++) {
                    int row = wn * 64 + half * 32 + p * 16 + (g >> 1) * 8 + (lane & 7);
                    uint32_t boff = (uint32_t)row * 80 + ks * 32 + (g & 1) * 16;
                    ldsm4(bh[p], bHi + boff);
                    ldsm4(bl[p], bLo + boff);
                }
#pragma unroll
                for (int mt = 0; mt < 2; mt++)
#pragma unroll
                    for (int p = 0; p < 2; p++)
#pragma unroll
                        for (int pt = 0; pt < 2; pt++) {
                            int nt = half * 4 + p * 2 + pt;
                            mma16816(acc[mt][nt], ah[mt], &bh[p][pt * 2]);
                            mma16816(acc[mt][nt], al[mt], &bh[p][pt * 2]);
                            mma16816(acc[mt][nt], ah[mt], &bl[p][pt * 2]);
                        }
            }
        }
        __syncthreads();
    }

#pragma unroll
    for (int mt = 0; mt < 2; mt++) {
        int r0 = by * 128 + wm * 32 + mt * 16 + (lane >> 2);
#pragma unroll
        for (int nt = 0; nt < 8; nt++) {
            int c0 = bx * 128 + wn * 64 + nt * 8 + (lane & 3) * 2;
            float b0 = bias[c0], b1 = bias[c0 + 1];
            C[(size_t)r0 * N + c0]           = acc[mt][nt][0] + b0;
            C[(size_t)r0 * N + c0 + 1]       = acc[mt][nt][1] + b1;
            C[(size_t)(r0 + 8) * N + c0]     = acc[mt][nt][2] + b0;
            C[(size_t)(r0 + 8) * N + c0 + 1] = acc[mt][nt][3] + b1;
        }
    }
}

// ================= tau: split-K (32 slices) tiled GEMM over gelu(qkv) =================
__global__ __launch_bounds__(256)
void tau_gemm_kernel(const float* __restrict__ qkv, const float* __restrict__ wq,
                     const float* __restrict__ wv, float* __restrict__ part) {
    __shared__ float sA[32][129];
    __shared__ float sW[32][65];
    const int tid = threadIdx.x;
    const int t0 = blockIdx.x * 128;
    const int k0 = blockIdx.y * 192;
    const int ty = tid >> 4, tx = tid & 15;

    float acc[8][4];
#pragma unroll
    for (int i = 0; i < 8; i++)
#pragma unroll
        for (int j = 0; j < 4; j++) acc[i][j] = 0.f;

    for (int kt = 0; kt < 6; kt++) {
        int kb = k0 + kt * 32;
        for (int e = tid; e < 4096; e += 256) {
            int tok = e >> 5, k = e & 31;
            float x = qkv[(size_t)(t0 + tok) * QKVD + kb + k];
            sA[k][tok] = 0.5f * x * (1.0f + erff(x * 0.70710678118654752f));
        }
        for (int e = tid; e < 2048; e += 256) {
            int n = e >> 5, k = e & 31;
            const float* w = (n < 32) ? (wq + (size_t)n * QKVD) : (wv + (size_t)(n - 32) * QKVD);
            sW[k][n] = w[kb + k];
        }
        __syncthreads();
#pragma unroll
        for (int k = 0; k < 32; k++) {
            float a[8], b[4];
#pragma unroll
            for (int i = 0; i < 8; i++) a[i] = sA[k][ty * 8 + i];
#pragma unroll
            for (int j = 0; j < 4; j++) b[j] = sW[k][tx * 4 + j];
#pragma unroll
            for (int i = 0; i < 8; i++)
#pragma unroll
                for (int j = 0; j < 4; j++) acc[i][j] += a[i] * b[j];
        }
        __syncthreads();
    }
#pragma unroll
    for (int i = 0; i < 8; i++)
#pragma unroll
        for (int j = 0; j < 4; j++)
            part[((size_t)blockIdx.y * T_ + t0 + ty * 8 + i) * 64 + tx * 4 + j] = acc[i][j];
}

__global__ __launch_bounds__(256)
void tau_finish_kernel(const float* __restrict__ part, const float* __restrict__ alpha,
                       const int* __restrict__ positions,
                       float* __restrict__ tauq, float* __restrict__ tauv) {
    int idx = blockIdx.x * 256 + threadIdx.x;
    if (idx >= T_ * 64) return;
    int t = idx >> 6, o = idx & 63;
    float s = 0.f;
#pragma unroll
    for (int ks = 0; ks < 32; ks++) s += part[(size_t)ks * T_ * 64 + idx];
    int h = o & 31;
    float pl = logf(fmaxf((float)positions[t] + 1.0f, 1e-6f));
    float tp = 0.5f + 1.0f / (1.0f + expf(-alpha[h] * pl));
    float v = tanhf(s) + tp;
    if (o < 32) tauq[t * NH + h] = v;
    else        tauv[t * NH + h] = v;
}

// ================= prep: tau scaling + NeoX RoPE -> bf16 hi/lo planes [H][T][D] =================
__global__ __launch_bounds__(256)
void prep_kernel(const float* __restrict__ qkv, const int* __restrict__ positions,
                 const float* __restrict__ tauq, const float* __restrict__ tauv,
                 __nv_bfloat16* __restrict__ Qhi, __nv_bfloat16* __restrict__ Qlo,
                 __nv_bfloat16* __restrict__ Khi, __nv_bfloat16* __restrict__ Klo,
                 __nv_bfloat16* __restrict__ Vhi, __nv_bfloat16* __restrict__ Vlo) {
    const int t = blockIdx.x;
    const float p = (float)positions[t];
    const float* row = qkv + (size_t)t * QKVD;

    for (int e = threadIdx.x; e < DIM_; e += 256) {
        int h = e >> 6;
        int d = e & 63;
        float tq = tauq[t * NH + h];
        float tv = tauv[t * NH + h];

        float qo = row[e] * tq;
        float ko = row[DIM_ + e];
        float vo = row[2 * DIM_ + e] * tv;

        if (d < 32) {
            int i = (d < 16) ? d : (d - 16);
            float ang = p * exp2f(-(float)i * 1.2457230355827609f);
            float s, c;
            sincosf(ang, &s, &c);
            if (d < 16) {
                float q2 = row[e + 16] * tq;
                float k2 = row[DIM_ + e + 16];
                qo = qo * c - q2 * s;
                ko = ko * c - k2 * s;
            } else {
                float q1 = row[e - 16] * tq;
                float k1 = row[DIM_ + e - 16];
                qo = qo * c + q1 * s;
                ko = ko * c + k1 * s;
            }
        }
        qo *= 0.125f;   // fold score scale into Q (commutes with rotation)
        size_t o = (size_t)h * T_ * HD + (size_t)t * HD + d;
        __nv_bfloat16 qh = __float2bfloat16_rn(qo);
        __nv_bfloat16 kh = __float2bfloat16_rn(ko);
        __nv_bfloat16 vh = __float2bfloat16_rn(vo);
        Qhi[o] = qh; Qlo[o] = __float2bfloat16_rn(qo - __bfloat162float(qh));
        Khi[o] = kh; Klo[o] = __float2bfloat16_rn(ko - __bfloat162float(kh));
        Vhi[o] = vh; Vlo[o] = __float2bfloat16_rn(vo - __bfloat162float(vh));
    }
}

// ================= HMMA flash attention =================
// 128 q-rows/block (8 warps x 16), 64-key tiles, 3-stage cp.async,
// split-bf16 QK (3 terms) and PV (3 terms). Writes attn as bf16 hi/lo planes.
#define FROW 144                      // padded smem row bytes (64 bf16 + 8 pad)
#define FQL_OFF (128 * FROW)          // 18432
#define FSTG0   (2 * 128 * FROW)      // 36864
#define FSTG_BYTES (4 * 64 * FROW)    // 36864
#define FKH 0
#define FKL (64 * FROW)
#define FVH (2 * 64 * FROW)
#define FVL (3 * 64 * FROW)
#define FLASH2_SMEM (FSTG0 + 3 * FSTG_BYTES)   // 147456

__global__ __launch_bounds__(256, 1)
void flash_hmma_kernel(const __nv_bfloat16* __restrict__ Qhi, const __nv_bfloat16* __restrict__ Qlo,
                       const __nv_bfloat16* __restrict__ Khi, const __nv_bfloat16* __restrict__ Klo,
                       const __nv_bfloat16* __restrict__ Vhi, const __nv_bfloat16* __restrict__ Vlo,
                       __nv_bfloat16* __restrict__ Ahi, __nv_bfloat16* __restrict__ Alo) {
    extern __shared__ char smem[];
    const uint32_t sb = smem_u32(smem);
    const int tid = threadIdx.x;
    const int wid = tid >> 5;
    const int lane = tid & 31;
    const int h = blockIdx.y;
    const int qt = (int)gridDim.x - 1 - (int)blockIdx.x;   // long blocks first
    const int q0 = qt * 128;
    const size_t hb = (size_t)h * T_ * HD;
    const int nkt = 2 * qt + 2;

    // ---- Q tile load: 2 planes x 128 rows x 8 chunks = 2048 chunks ----
#pragma unroll
    for (int i = 0; i < 8; i++) {
        int c = tid + i * 256;
        int pl = c >> 10;
        int r = (c >> 3) & 127;
        int k8 = c & 7;
        const __nv_bfloat16* src = (pl ? Qlo : Qhi) + hb + (size_t)(q0 + r) * HD + k8 * 8;
        cp_async16(sb + pl * FQL_OFF + (uint32_t)r * FROW + k8 * 16, src);
    }
    CP_COMMIT();

    auto load_kv = [&](int kt) {
        if (kt < nkt) {
            uint32_t stg = sb + FSTG0 + (kt % 3) * FSTG_BYTES;
#pragma unroll
            for (int i = 0; i < 8; i++) {
                int c = tid + i * 256;
                int pl = c >> 9;              // 0..3 : KH KL VH VL
                int r = (c >> 3) & 63;
                int k8 = c & 7;
                const __nv_bfloat16* base =
                    (pl == 0) ? Khi : (pl == 1) ? Klo : (pl == 2) ? Vhi : Vlo;
                cp_async16(stg + pl * (64 * FROW) + (uint32_t)r * FROW + k8 * 16,
                           base + hb + (size_t)(kt * 64 + r) * HD + k8 * 8);
            }
        }
        CP_COMMIT();
    };
    load_kv(0); load_kv(1); load_kv(2);

    CP_WAIT(3);          // Q plane done (3 stage groups may be pending)
    __syncthreads();

    // ---- Q fragments (held in registers for the whole kernel) ----
    uint32_t aqh[4][4], aql[4][4];
#pragma unroll
    for (int ks = 0; ks < 4; ks++) {
        uint32_t addr = sb + (uint32_t)(wid * 16 + (lane & 15)) * FROW + ks * 32 + (lane >> 4) * 16;
        ldsm4(aqh[ks], addr);
        ldsm4(aql[ks], addr + FQL_OFF);
    }

    float m0 = -1e30f, m1 = -1e30f, l0 = 0.f, l1 = 0.f;
    float O[8][4];
#pragma unroll
    for (int nf = 0; nf < 8; nf++)
#pragma unroll
        for (int c = 0; c < 4; c++) O[nf][c] = 0.f;

    for (int kt = 0; kt < nkt; kt++) {
        CP_WAIT(2);
        __syncthreads();
        const bool active = (kt * 64 <= q0 + wid * 16 + 15);
        const uint32_t stg = sb + FSTG0 + (kt % 3) * FSTG_BYTES;

        if (active) {
            float S[8][4];
#pragma unroll
            for (int nf = 0; nf < 8; nf++)
#pragma unroll
                for (int c = 0; c < 4; c++) S[nf][c] = 0.f;

            // ---- S = Q K^T (split 3-term) ----
#pragma unroll
            for (int ks = 0; ks < 4; ks++) {
                uint32_t bh[4][4], bl[4][4];
#pragma unroll
                for (int kp = 0; kp < 4; kp++) {
                    uint32_t ka = stg + (uint32_t)(kp * 16 + ((lane >> 4) << 3) + (lane & 7)) * FROW
                                  + ks * 32 + ((lane >> 3) & 1) * 16;
                    ldsm4(bh[kp], ka + FKH);
                    ldsm4(bl[kp], ka + FKL);
                }
#pragma unroll
                for (int kp = 0; kp < 4; kp++)
#pragma unroll
                    for (int half = 0; half < 2; half++) {
                        int nf = kp * 2 + half;
                        mma16816(S[nf], aqh[ks], &bh[kp][half * 2]);
                        mma16816(S[nf], aql[ks], &bh[kp][half * 2]);
                        mma16816(S[nf], aqh[ks], &bl[kp][half * 2]);
                    }
            }

            // ---- causal mask (only the two diagonal tiles) ----
            if (kt >= 2 * qt) {
                int rbase = q0 + wid * 16 + (lane >> 2);
                int cbase = kt * 64 + (lane & 3) * 2;
#pragma unroll
                for (int nf = 0; nf < 8; nf++)
#pragma unroll
                    for (int c = 0; c < 4; c++) {
                        int row = rbase + ((c >> 1) & 1) * 8;
                        int col = cbase + nf * 8 + (c & 1);
                        if (col > row) S[nf][c] = -1e30f;
                    }
            }

            // ---- online softmax (rows j=0: regs 0,1 ; j=1: regs 2,3) ----
#pragma unroll
            for (int j = 0; j < 2; j++) {
                float& mj = j ? m1 : m0;
                float& lj = j ? l1 : l0;
                float rm = -1e30f;
#pragma unroll
                for (int nf = 0; nf < 8; nf++) {
                    rm = fmaxf(rm, S[nf][2 * j]);
                    rm = fmaxf(rm, S[nf][2 * j + 1]);
                }
                rm = fmaxf(rm, __shfl_xor_sync(0xffffffffu, rm, 1));
                rm = fmaxf(rm, __shfl_xor_sync(0xffffffffu, rm, 2));
                float mn = fmaxf(mj, rm);
                float alpha = __expf(mj - mn);
                float rs = 0.f;
#pragma unroll
                for (int nf = 0; nf < 8; nf++) {
                    float p0 = __expf(S[nf][2 * j] - mn);
                    float p1 = __expf(S[nf][2 * j + 1] - mn);
                    S[nf][2 * j] = p0; S[nf][2 * j + 1] = p1;
                    rs += p0 + p1;
                }
                rs += __shfl_xor_sync(0xffffffffu, rs, 1);
                rs += __shfl_xor_sync(0xffffffffu, rs, 2);
                lj = lj * alpha + rs;
                mj = mn;
#pragma unroll
                for (int nf = 0; nf < 8; nf++) {
                    O[nf][2 * j] *= alpha;
                    O[nf][2 * j + 1] *= alpha;
                }
            }

            // ---- O += P V (split 3-term), P fragments built in-register ----
#pragma unroll
            for (int ks = 0; ks < 4; ks++) {
                uint32_t ah[4], al[4];
#pragma unroll
                for (int q = 0; q < 4; q++) {
                    int sf = 2 * ks + (q >> 1);
                    int c0 = (q & 1) * 2;
                    float p0 = S[sf][c0], p1 = S[sf][c0 + 1];
                    float h0 = __bfloat162float(__float2bfloat16_rn(p0));
                    float h1 = __bfloat162float(__float2bfloat16_rn(p1));
                    ah[q] = pack_bf2(h0, h1);
                    al[q] = pack_bf2(p0 - h0, p1 - h1);
                }
#pragma unroll
                for (int dp = 0; dp < 4; dp++) {
                    uint32_t va = stg + (uint32_t)(ks * 16 + ((lane >> 3) & 1) * 8 + (lane & 7)) * FROW
                                  + dp * 32 + (lane >> 4) * 16;
                    uint32_t vh[4], vl[4];
                    ldsm4t(vh, va + FVH);
                    ldsm4t(vl, va + FVL);
                    mma16816(O[2 * dp],     ah, &vh[0]);
                    mma16816(O[2 * dp],     al, &vh[0]);
                    mma16816(O[2 * dp],     ah, &vl[0]);
                    mma16816(O[2 * dp + 1], ah, &vh[2]);
                    mma16816(O[2 * dp + 1], al, &vh[2]);
                    mma16816(O[2 * dp + 1], ah, &vl[2]);
                }
            }
        }
        __syncthreads();
        load_kv(kt + 3);
    }

    // ---- epilogue: normalize + split to bf16 hi/lo planes ----
    float inv0 = 1.0f / l0;
    float inv1 = 1.0f / l1;
    int r0 = q0 + wid * 16 + (lane >> 2);
#pragma unroll
    for (int nf = 0; nf < 8; nf++)
#pragma unroll
        for (int j = 0; j < 2; j++) {
            float inv = j ? inv1 : inv0;
            float v0 = O[nf][2 * j] * inv;
            float v1 = O[nf][2 * j + 1] * inv;
            int t = r0 + j * 8;
            int col = h * 64 + nf * 8 + (lane & 3) * 2;
            float h0 = __bfloat162float(__float2bfloat16_rn(v0));
            float h1 = __bfloat162float(__float2bfloat16_rn(v1));
            *(uint32_t*)&Ahi[(size_t)t * DIM_ + col] = pack_bf2(h0, h1);
            *(uint32_t*)&Alo[(size_t)t * DIM_ + col] = pack_bf2(v0 - h0, v1 - h1);
        }
}

// ================= host launch =================
extern "C" void kernel_launch(void* const* d_in, const int* in_sizes, int n_in,
                              void* d_out, int out_size) {
    const int*   positions = (const int*)d_in[0];
    const float* hidden    = (const float*)d_in[1];
    const float* Wqkv      = (const float*)d_in[2];
    const float* bqkv      = (const float*)d_in[3];
    const float* Wout      = (const float*)d_in[4];
    const float* bout      = (const float*)d_in[5];
    const float* tau_alpha = (const float*)d_in[6];
    const float* tau_wq    = (const float*)d_in[7];
    const float* tau_wv    = (const float*)d_in[8];
    float* out = (float*)d_out;

    float *qkv, *tauq, *tauv, *taupart;
    __nv_bfloat16 *Ahi, *Alo, *Whi, *Wlo, *Qhi, *Qlo, *Khi, *Klo, *Vhi, *Vlo;
    cudaGetSymbolAddress((void**)&qkv,     g_qkv);
    cudaGetSymbolAddress((void**)&tauq,    g_tauq);
    cudaGetSymbolAddress((void**)&tauv,    g_tauv);
    cudaGetSymbolAddress((void**)&taupart, g_taupart);
    cudaGetSymbolAddress((void**)&Ahi,     g_Ahi);
    cudaGetSymbolAddress((void**)&Alo,     g_Alo);
    cudaGetSymbolAddress((void**)&Whi,     g_Whi);
    cudaGetSymbolAddress((void**)&Wlo,     g_Wlo);
    cudaGetSymbolAddress((void**)&Qhi,     g_Qhi);
    cudaGetSymbolAddress((void**)&Qlo,     g_Qlo);
    cudaGetSymbolAddress((void**)&Khi,     g_Khi);
    cudaGetSymbolAddress((void**)&Klo,     g_Klo);
    cudaGetSymbolAddress((void**)&Vhi,     g_Vhi);
    cudaGetSymbolAddress((void**)&Vlo,     g_Vlo);

    cudaFuncSetAttribute(gemm_hmma_kernel, cudaFuncAttributeMaxDynamicSharedMemorySize, GSMEM);
    cudaFuncSetAttribute(flash_hmma_kernel, cudaFuncAttributeMaxDynamicSharedMemorySize, FLASH2_SMEM);

    // 1. decompose hidden + Wqkv into bf16 hi/lo planes
    decomp_kernel<<<(T_ * DIM_ / 4 + 255) / 256, 256>>>(hidden, Ahi, Alo, T_ * DIM_ / 4);
    decomp_kernel<<<(QKVD * DIM_ / 4 + 255) / 256, 256>>>(Wqkv, Whi, Wlo, QKVD * DIM_ / 4);
    // 2. qkv = hidden @ Wqkv^T + bqkv
    gemm_hmma_kernel<<<dim3(QKVD / 128, T_ / 128), 256, GSMEM>>>(
        Ahi, Alo, Whi, Wlo, bqkv, qkv, QKVD, DIM_);
    // 3. tau projections
    tau_gemm_kernel<<<dim3(T_ / 128, 32), 256>>>(qkv, tau_wq, tau_wv, taupart);
    tau_finish_kernel<<<(T_ * 64 + 255) / 256, 256>>>(taupart, tau_alpha, positions, tauq, tauv);
    // 4. scale + rope -> bf16 hi/lo Q/K/V planes
    prep_kernel<<<T_, 256>>>(qkv, positions, tauq, tauv, Qhi, Qlo, Khi, Klo, Vhi, Vlo);
    // 5. causal flash attention (HMMA) -> attn hi/lo planes
    flash_hmma_kernel<<<dim3(T_ / 128, NH), 256, FLASH2_SMEM>>>(
        Qhi, Qlo, Khi, Klo, Vhi, Vlo, Ahi, Alo);
    // 6. out = attn @ Wout^T + bout
    decomp_kernel<<<(DIM_ * DIM_ / 4 + 255) / 256, 256>>>(Wout, Whi, Wlo, DIM_ * DIM_ / 4);
    gemm_hmma_kernel<<<dim3(DIM_ / 128, T_ / 128), 256, GSMEM>>>(
        Ahi, Alo, Whi, Wlo, bout, out, DIM_, DIM_);
}

// round 5
// speedup vs baseline: 2.8713x; 1.6587x over previous
#include <cuda_runtime.h>
#include <cuda_bf16.h>
#include <math.h>
#include <stdint.h>

#define T_ 2048
#define DIM_ 2048
#define NH 32
#define HD 64
#define QKVD 6144

// ---------------- scratch ----------------
__device__ float g_qkv[T_ * QKVD];
__device__ float g_tauq[T_ * NH];
__device__ float g_tauv[T_ * NH];
__device__ float g_taupart[8 * T_ * 64];
__device__ __nv_bfloat16 g_Ahi[T_ * DIM_];
__device__ __nv_bfloat16 g_Alo[T_ * DIM_];
__device__ __nv_bfloat16 g_Whi[QKVD * DIM_];
__device__ __nv_bfloat16 g_Wlo[QKVD * DIM_];
__device__ __nv_bfloat16 g_Ghi[T_ * QKVD];     // gelu(qkv) hi plane
__device__ __nv_bfloat16 g_Glo[T_ * QKVD];
__device__ __nv_bfloat16 g_Twhi[64 * QKVD];    // stacked tau_wq/tau_wv planes
__device__ __nv_bfloat16 g_Twlo[64 * QKVD];
__device__ __nv_bfloat16 g_Qhi[NH * T_ * HD];
__device__ __nv_bfloat16 g_Qlo[NH * T_ * HD];
__device__ __nv_bfloat16 g_Khi[NH * T_ * HD];
__device__ __nv_bfloat16 g_Klo[NH * T_ * HD];
__device__ __nv_bfloat16 g_Vhi[NH * T_ * HD];
__device__ __nv_bfloat16 g_Vlo[NH * T_ * HD];

// ================= helpers =================
__device__ __forceinline__ uint32_t smem_u32(const void* p) {
    uint32_t a;
    asm("{ .reg .u64 t; cvta.to.shared.u64 t, %1; cvt.u32.u64 %0, t; }" : "=r"(a) : "l"(p));
    return a;
}
__device__ __forceinline__ void ldsm4(uint32_t* r, uint32_t addr) {
    asm volatile("ldmatrix.sync.aligned.m8n8.x4.shared.b16 {%0,%1,%2,%3}, [%4];"
        : "=r"(r[0]), "=r"(r[1]), "=r"(r[2]), "=r"(r[3]) : "r"(addr));
}
__device__ __forceinline__ void ldsm4t(uint32_t* r, uint32_t addr) {
    asm volatile("ldmatrix.sync.aligned.m8n8.x4.trans.shared.b16 {%0,%1,%2,%3}, [%4];"
        : "=r"(r[0]), "=r"(r[1]), "=r"(r[2]), "=r"(r[3]) : "r"(addr));
}
__device__ __forceinline__ void mma16816(float* d, const uint32_t* a, const uint32_t* b) {
    asm volatile("mma.sync.aligned.m16n8k16.row.col.f32.bf16.bf16.f32 "
        "{%0,%1,%2,%3}, {%4,%5,%6,%7}, {%8,%9}, {%0,%1,%2,%3};"
        : "+f"(d[0]), "+f"(d[1]), "+f"(d[2]), "+f"(d[3])
        : "r"(a[0]), "r"(a[1]), "r"(a[2]), "r"(a[3]), "r"(b[0]), "r"(b[1]));
}
__device__ __forceinline__ void cp_async16(uint32_t dst, const void* src) {
    asm volatile("cp.async.cg.shared.global [%0], [%1], 16;" :: "r"(dst), "l"(src) : "memory");
}
#define CP_COMMIT() asm volatile("cp.async.commit_group;" ::: "memory")
#define CP_WAIT(n)  asm volatile("cp.async.wait_group %0;" :: "n"(n) : "memory")

__device__ __forceinline__ uint32_t pack_bf2(float lo, float hi) {
    __nv_bfloat162 t = __floats2bfloat162_rn(lo, hi);
    return *reinterpret_cast<uint32_t*>(&t);
}

// ================= split-bf16 decomposition =================
__global__ __launch_bounds__(256)
void decomp_kernel(const float* __restrict__ in, __nv_bfloat16* __restrict__ hi,
                   __nv_bfloat16* __restrict__ lo, int n4) {
    int i = blockIdx.x * 256 + threadIdx.x;
    if (i >= n4) return;
    float4 v = ((const float4*)in)[i];
    __nv_bfloat16 h0 = __float2bfloat16_rn(v.x);
    __nv_bfloat16 h1 = __float2bfloat16_rn(v.y);
    __nv_bfloat16 h2 = __float2bfloat16_rn(v.z);
    __nv_bfloat16 h3 = __float2bfloat16_rn(v.w);
    __nv_bfloat16 l0 = __float2bfloat16_rn(v.x - __bfloat162float(h0));
    __nv_bfloat16 l1 = __float2bfloat16_rn(v.y - __bfloat162float(h1));
    __nv_bfloat16 l2 = __float2bfloat16_rn(v.z - __bfloat162float(h2));
    __nv_bfloat16 l3 = __float2bfloat16_rn(v.w - __bfloat162float(h3));
    ((__nv_bfloat162*)hi)[i * 2 + 0] = __halves2bfloat162(h0, h1);
    ((__nv_bfloat162*)hi)[i * 2 + 1] = __halves2bfloat162(h2, h3);
    ((__nv_bfloat162*)lo)[i * 2 + 0] = __halves2bfloat162(l0, l1);
    ((__nv_bfloat162*)lo)[i * 2 + 1] = __halves2bfloat162(l2, l3);
}

// ================= HMMA split-bf16 GEMM, 64x32 warp tiles =================
// C[M,N] = A[M,K] @ B[N,K]^T + bias[N]; optional fused gelu+decomp epilogue.
#define MAT_BYTES  (128 * 80)
#define STAGE_BYTES (4 * MAT_BYTES)
#define GSMEM (3 * STAGE_BYTES)

__global__ __launch_bounds__(256)
void gemm_hmma_kernel(const __nv_bfloat16* __restrict__ Ahi, const __nv_bfloat16* __restrict__ Alo,
                      const __nv_bfloat16* __restrict__ Bhi, const __nv_bfloat16* __restrict__ Blo,
                      const float* __restrict__ bias, float* __restrict__ C,
                      __nv_bfloat16* __restrict__ Ghi, __nv_bfloat16* __restrict__ Glo,
                      int N, int K) {
    extern __shared__ char smem[];
    const uint32_t sbase = smem_u32(smem);
    const int tid = threadIdx.x;
    const int wid = tid >> 5;
    const int lane = tid & 31;
    const int wm = wid >> 2;        // 0..1 : 64-row block
    const int wn = wid & 3;         // 0..3 : 32-col block
    const int bx = blockIdx.x, by = blockIdx.y;
    const int nch = K / 32;

    const int lrow0 = tid >> 2;
    const int lc0 = tid & 3;

    float acc[4][4][4];
#pragma unroll
    for (int mt = 0; mt < 4; mt++)
#pragma unroll
        for (int nt = 0; nt < 4; nt++)
#pragma unroll
            for (int r = 0; r < 4; r++) acc[mt][nt][r] = 0.f;

    auto load_stage = [&](int s, int ci) {
        uint32_t st = sbase + s * STAGE_BYTES;
        int k0 = ci * 32;
#pragma unroll
        for (int it = 0; it < 2; it++) {
            int row = lrow0 + it * 64;
            uint32_t so = (uint32_t)row * 80 + lc0 * 16;
            size_t ga = ((size_t)(by * 128 + row) * K + k0 + lc0 * 8);
            size_t gb = ((size_t)(bx * 128 + row) * K + k0 + lc0 * 8);
            cp_async16(st + so,                 Ahi + ga);
            cp_async16(st + MAT_BYTES + so,     Alo + ga);
            cp_async16(st + 2 * MAT_BYTES + so, Bhi + gb);
            cp_async16(st + 3 * MAT_BYTES + so, Blo + gb);
        }
        CP_COMMIT();
    };

    load_stage(0, 0);
    load_stage(1, 1);

    for (int ci = 0; ci < nch; ci++) {
        if (ci == nch - 1) { CP_WAIT(0); } else { CP_WAIT(1); }
        __syncthreads();

        if (ci + 2 < nch) load_stage((ci + 2) % 3, ci + 2);

        uint32_t st = sbase + (ci % 3) * STAGE_BYTES;
        uint32_t aHi = st, aLo = st + MAT_BYTES;
        uint32_t bHi = st + 2 * MAT_BYTES, bLo = st + 3 * MAT_BYTES;
        const int g = lane >> 3;

#pragma unroll
        for (int ks = 0; ks < 2; ks++) {
            uint32_t ah[4][4], al[4][4];
#pragma unroll
            for (int mt = 0; mt < 4; mt++) {
                uint32_t aoff = (uint32_t)(wm * 64 + mt * 16 + (lane & 15)) * 80
                                + ks * 32 + (lane >> 4) * 16;
                ldsm4(ah[mt], aHi + aoff);
                ldsm4(al[mt], aLo + aoff);
            }
            uint32_t bh[2][4], bl[2][4];
#pragma unroll
            for (int p = 0; p < 2; p++) {
                int row = wn * 32 + p * 16 + (g >> 1) * 8 + (lane & 7);
                uint32_t boff = (uint32_t)row * 80 + ks * 32 + (g & 1) * 16;
                ldsm4(bh[p], bHi + boff);
                ldsm4(bl[p], bLo + boff);
            }
#pragma unroll
            for (int mt = 0; mt < 4; mt++)
#pragma unroll
                for (int p = 0; p < 2; p++)
#pragma unroll
                    for (int pt = 0; pt < 2; pt++) {
                        int nt = p * 2 + pt;
                        mma16816(acc[mt][nt], ah[mt], &bh[p][pt * 2]);
                        mma16816(acc[mt][nt], al[mt], &bh[p][pt * 2]);
                        mma16816(acc[mt][nt], ah[mt], &bl[p][pt * 2]);
                    }
        }
        __syncthreads();
    }

    // ---- epilogue ----
    const bool do_gelu = (Ghi != nullptr);
#pragma unroll
    for (int mt = 0; mt < 4; mt++) {
        int r0 = by * 128 + wm * 64 + mt * 16 + (lane >> 2);
#pragma unroll
        for (int nt = 0; nt < 4; nt++) {
            int c0 = bx * 128 + wn * 32 + nt * 8 + (lane & 3) * 2;
            float b0 = bias[c0], b1 = bias[c0 + 1];
#pragma unroll
            for (int rr = 0; rr < 2; rr++) {
                int r = r0 + rr * 8;
                float v0 = acc[mt][nt][rr * 2 + 0] + b0;
                float v1 = acc[mt][nt][rr * 2 + 1] + b1;
                *(float2*)&C[(size_t)r * N + c0] = make_float2(v0, v1);
                if (do_gelu) {
                    float g0 = 0.5f * v0 * (1.0f + erff(v0 * 0.70710678118654752f));
                    float g1 = 0.5f * v1 * (1.0f + erff(v1 * 0.70710678118654752f));
                    float h0 = __bfloat162float(__float2bfloat16_rn(g0));
                    float h1 = __bfloat162float(__float2bfloat16_rn(g1));
                    *(uint32_t*)&Ghi[(size_t)r * N + c0] = pack_bf2(h0, h1);
                    *(uint32_t*)&Glo[(size_t)r * N + c0] = pack_bf2(g0 - h0, g1 - h1);
                }
            }
        }
    }
}

// ================= tau: HMMA split-K GEMM: part = G @ Tw^T =================
// M=2048 (128/block), N=64, K=6144 split 8 ways (768/block). 8 warps 4x2.
#define TAPL 10240            // A plane bytes: 128*80
#define TBPL 5120             // B plane bytes: 64*80
#define TSTAGE (2 * TAPL + 2 * TBPL)   // 30720
#define TSMEM (3 * TSTAGE)

__global__ __launch_bounds__(256)
void tau_hmma_kernel(const __nv_bfloat16* __restrict__ Ghi, const __nv_bfloat16* __restrict__ Glo,
                     const __nv_bfloat16* __restrict__ Twhi, const __nv_bfloat16* __restrict__ Twlo,
                     float* __restrict__ part) {
    extern __shared__ char smem[];
    const uint32_t sbase = smem_u32(smem);
    const int tid = threadIdx.x;
    const int wid = tid >> 5;
    const int lane = tid & 31;
    const int wm = wid >> 1;      // 0..3 : 32-row block
    const int wn = wid & 1;       // 0..1 : 32-col block
    const int t0 = blockIdx.x * 128;
    const int kbase = blockIdx.y * 768;

    float acc[2][4][4];
#pragma unroll
    for (int mt = 0; mt < 2; mt++)
#pragma unroll
        for (int nt = 0; nt < 4; nt++)
#pragma unroll
            for (int r = 0; r < 4; r++) acc[mt][nt][r] = 0.f;

    auto load_stage = [&](int s, int ci) {
        uint32_t st = sbase + s * TSTAGE;
        int k0 = kbase + ci * 32;
#pragma unroll
        for (int i = 0; i < 6; i++) {
            int c = tid + i * 256;
            if (c < 1024) {
                int pl = c >> 9, r = (c >> 2) & 127, k4 = c & 3;
                cp_async16(st + pl * TAPL + (uint32_t)r * 80 + k4 * 16,
                           (pl ? Glo : Ghi) + (size_t)(t0 + r) * QKVD + k0 + k4 * 8);
            } else {
                int c2 = c - 1024;
                int pl = c2 >> 8, r = (c2 >> 2) & 63, k4 = c2 & 3;
                cp_async16(st + 2 * TAPL + pl * TBPL + (uint32_t)r * 80 + k4 * 16,
                           (pl ? Twlo : Twhi) + (size_t)r * QKVD + k0 + k4 * 8);
            }
        }
        CP_COMMIT();
    };

    load_stage(0, 0);
    load_stage(1, 1);

    for (int ci = 0; ci < 24; ci++) {
        if (ci == 23) { CP_WAIT(0); } else { CP_WAIT(1); }
        __syncthreads();
        if (ci + 2 < 24) load_stage((ci + 2) % 3, ci + 2);

        uint32_t st = sbase + (ci % 3) * TSTAGE;
        const int g = lane >> 3;
#pragma unroll
        for (int ks = 0; ks < 2; ks++) {
            uint32_t ah[2][4], al[2][4];
#pragma unroll
            for (int mt = 0; mt < 2; mt++) {
                uint32_t aoff = (uint32_t)(wm * 32 + mt * 16 + (lane & 15)) * 80
                                + ks * 32 + (lane >> 4) * 16;
                ldsm4(ah[mt], st + aoff);
                ldsm4(al[mt], st + TAPL + aoff);
            }
            uint32_t bh[2][4], bl[2][4];
#pragma unroll
            for (int p = 0; p < 2; p++) {
                int row = wn * 32 + p * 16 + (g >> 1) * 8 + (lane & 7);
                uint32_t boff = (uint32_t)row * 80 + ks * 32 + (g & 1) * 16;
                ldsm4(bh[p], st + 2 * TAPL + boff);
                ldsm4(bl[p], st + 2 * TAPL + TBPL + boff);
            }
#pragma unroll
            for (int mt = 0; mt < 2; mt++)
#pragma unroll
                for (int p = 0; p < 2; p++)
#pragma unroll
                    for (int pt = 0; pt < 2; pt++) {
                        int nt = p * 2 + pt;
                        mma16816(acc[mt][nt], ah[mt], &bh[p][pt * 2]);
                        mma16816(acc[mt][nt], al[mt], &bh[p][pt * 2]);
                        mma16816(acc[mt][nt], ah[mt], &bl[p][pt * 2]);
                    }
        }
        __syncthreads();
    }

    float* pb = part + (size_t)blockIdx.y * T_ * 64;
#pragma unroll
    for (int mt = 0; mt < 2; mt++) {
        int r0 = t0 + wm * 32 + mt * 16 + (lane >> 2);
#pragma unroll
        for (int nt = 0; nt < 4; nt++) {
            int c0 = wn * 32 + nt * 8 + (lane & 3) * 2;
            *(float2*)&pb[(size_t)r0 * 64 + c0]       = make_float2(acc[mt][nt][0], acc[mt][nt][1]);
            *(float2*)&pb[(size_t)(r0 + 8) * 64 + c0] = make_float2(acc[mt][nt][2], acc[mt][nt][3]);
        }
    }
}

__global__ __launch_bounds__(256)
void tau_finish_kernel(const float* __restrict__ part, const float* __restrict__ alpha,
                       const int* __restrict__ positions,
                       float* __restrict__ tauq, float* __restrict__ tauv) {
    int idx = blockIdx.x * 256 + threadIdx.x;
    if (idx >= T_ * 64) return;
    int t = idx >> 6, o = idx & 63;
    float s = 0.f;
#pragma unroll
    for (int ks = 0; ks < 8; ks++) s += part[(size_t)ks * T_ * 64 + idx];
    int h = o & 31;
    float pl = logf(fmaxf((float)positions[t] + 1.0f, 1e-6f));
    float tp = 0.5f + 1.0f / (1.0f + expf(-alpha[h] * pl));
    float v = tanhf(s) + tp;
    if (o < 32) tauq[t * NH + h] = v;
    else        tauv[t * NH + h] = v;
}

// ================= prep: tau scaling + NeoX RoPE -> bf16 hi/lo planes =================
__global__ __launch_bounds__(256)
void prep_kernel(const float* __restrict__ qkv, const int* __restrict__ positions,
                 const float* __restrict__ tauq, const float* __restrict__ tauv,
                 __nv_bfloat16* __restrict__ Qhi, __nv_bfloat16* __restrict__ Qlo,
                 __nv_bfloat16* __restrict__ Khi, __nv_bfloat16* __restrict__ Klo,
                 __nv_bfloat16* __restrict__ Vhi, __nv_bfloat16* __restrict__ Vlo) {
    const int t = blockIdx.x;
    const float p = (float)positions[t];
    const float* row = qkv + (size_t)t * QKVD;

    for (int e = threadIdx.x; e < DIM_; e += 256) {
        int h = e >> 6;
        int d = e & 63;
        float tq = tauq[t * NH + h];
        float tv = tauv[t * NH + h];

        float qo = row[e] * tq;
        float ko = row[DIM_ + e];
        float vo = row[2 * DIM_ + e] * tv;

        if (d < 32) {
            int i = (d < 16) ? d : (d - 16);
            float ang = p * exp2f(-(float)i * 1.2457230355827609f);
            float s, c;
            sincosf(ang, &s, &c);
            if (d < 16) {
                float q2 = row[e + 16] * tq;
                float k2 = row[DIM_ + e + 16];
                qo = qo * c - q2 * s;
                ko = ko * c - k2 * s;
            } else {
                float q1 = row[e - 16] * tq;
                float k1 = row[DIM_ + e - 16];
                qo = qo * c + q1 * s;
                ko = ko * c + k1 * s;
            }
        }
        qo *= 0.125f;
        size_t o = (size_t)h * T_ * HD + (size_t)t * HD + d;
        __nv_bfloat16 qh = __float2bfloat16_rn(qo);
        __nv_bfloat16 kh = __float2bfloat16_rn(ko);
        __nv_bfloat16 vh = __float2bfloat16_rn(vo);
        Qhi[o] = qh; Qlo[o] = __float2bfloat16_rn(qo - __bfloat162float(qh));
        Khi[o] = kh; Klo[o] = __float2bfloat16_rn(ko - __bfloat162float(kh));
        Vhi[o] = vh; Vlo[o] = __float2bfloat16_rn(vo - __bfloat162float(vh));
    }
}

// ================= HMMA flash attention (as R4) =================
#define FROW 144
#define FQL_OFF (128 * FROW)
#define FSTG0   (2 * 128 * FROW)
#define FSTG_BYTES (4 * 64 * FROW)
#define FKH 0
#define FKL (64 * FROW)
#define FVH (2 * 64 * FROW)
#define FVL (3 * 64 * FROW)
#define FLASH2_SMEM (FSTG0 + 3 * FSTG_BYTES)

__global__ __launch_bounds__(256, 1)
void flash_hmma_kernel(const __nv_bfloat16* __restrict__ Qhi, const __nv_bfloat16* __restrict__ Qlo,
                       const __nv_bfloat16* __restrict__ Khi, const __nv_bfloat16* __restrict__ Klo,
                       const __nv_bfloat16* __restrict__ Vhi, const __nv_bfloat16* __restrict__ Vlo,
                       __nv_bfloat16* __restrict__ Ahi, __nv_bfloat16* __restrict__ Alo) {
    extern __shared__ char smem[];
    const uint32_t sb = smem_u32(smem);
    const int tid = threadIdx.x;
    const int wid = tid >> 5;
    const int lane = tid & 31;
    const int h = blockIdx.y;
    const int qt = (int)gridDim.x - 1 - (int)blockIdx.x;
    const int q0 = qt * 128;
    const size_t hb = (size_t)h * T_ * HD;
    const int nkt = 2 * qt + 2;

#pragma unroll
    for (int i = 0; i < 8; i++) {
        int c = tid + i * 256;
        int pl = c >> 10;
        int r = (c >> 3) & 127;
        int k8 = c & 7;
        const __nv_bfloat16* src = (pl ? Qlo : Qhi) + hb + (size_t)(q0 + r) * HD + k8 * 8;
        cp_async16(sb + pl * FQL_OFF + (uint32_t)r * FROW + k8 * 16, src);
    }
    CP_COMMIT();

    auto load_kv = [&](int kt) {
        if (kt < nkt) {
            uint32_t stg = sb + FSTG0 + (kt % 3) * FSTG_BYTES;
#pragma unroll
            for (int i = 0; i < 8; i++) {
                int c = tid + i * 256;
                int pl = c >> 9;
                int r = (c >> 3) & 63;
                int k8 = c & 7;
                const __nv_bfloat16* base =
                    (pl == 0) ? Khi : (pl == 1) ? Klo : (pl == 2) ? Vhi : Vlo;
                cp_async16(stg + pl * (64 * FROW) + (uint32_t)r * FROW + k8 * 16,
                           base + hb + (size_t)(kt * 64 + r) * HD + k8 * 8);
            }
        }
        CP_COMMIT();
    };
    load_kv(0); load_kv(1); load_kv(2);

    CP_WAIT(3);
    __syncthreads();

    uint32_t aqh[4][4], aql[4][4];
#pragma unroll
    for (int ks = 0; ks < 4; ks++) {
        uint32_t addr = sb + (uint32_t)(wid * 16 + (lane & 15)) * FROW + ks * 32 + (lane >> 4) * 16;
        ldsm4(aqh[ks], addr);
        ldsm4(aql[ks], addr + FQL_OFF);
    }

    float m0 = -1e30f, m1 = -1e30f, l0 = 0.f, l1 = 0.f;
    float O[8][4];
#pragma unroll
    for (int nf = 0; nf < 8; nf++)
#pragma unroll
        for (int c = 0; c < 4; c++) O[nf][c] = 0.f;

    for (int kt = 0; kt < nkt; kt++) {
        CP_WAIT(2);
        __syncthreads();
        const bool active = (kt * 64 <= q0 + wid * 16 + 15);
        const uint32_t stg = sb + FSTG0 + (kt % 3) * FSTG_BYTES;

        if (active) {
            float S[8][4];
#pragma unroll
            for (int nf = 0; nf < 8; nf++)
#pragma unroll
                for (int c = 0; c < 4; c++) S[nf][c] = 0.f;

#pragma unroll
            for (int ks = 0; ks < 4; ks++) {
                uint32_t bh[4][4], bl[4][4];
#pragma unroll
                for (int kp = 0; kp < 4; kp++) {
                    uint32_t ka = stg + (uint32_t)(kp * 16 + ((lane >> 4) << 3) + (lane & 7)) * FROW
                                  + ks * 32 + ((lane >> 3) & 1) * 16;
                    ldsm4(bh[kp], ka + FKH);
                    ldsm4(bl[kp], ka + FKL);
                }
#pragma unroll
                for (int kp = 0; kp < 4; kp++)
#pragma unroll
                    for (int half = 0; half < 2; half++) {
                        int nf = kp * 2 + half;
                        mma16816(S[nf], aqh[ks], &bh[kp][half * 2]);
                        mma16816(S[nf], aql[ks], &bh[kp][half * 2]);
                        mma16816(S[nf], aqh[ks], &bl[kp][half * 2]);
                    }
            }

            if (kt >= 2 * qt) {
                int rbase = q0 + wid * 16 + (lane >> 2);
                int cbase = kt * 64 + (lane & 3) * 2;
#pragma unroll
                for (int nf = 0; nf < 8; nf++)
#pragma unroll
                    for (int c = 0; c < 4; c++) {
                        int row = rbase + ((c >> 1) & 1) * 8;
                        int col = cbase + nf * 8 + (c & 1);
                        if (col > row) S[nf][c] = -1e30f;
                    }
            }

#pragma unroll
            for (int j = 0; j < 2; j++) {
                float& mj = j ? m1 : m0;
                float& lj = j ? l1 : l0;
                float rm = -1e30f;
#pragma unroll
                for (int nf = 0; nf < 8; nf++) {
                    rm = fmaxf(rm, S[nf][2 * j]);
                    rm = fmaxf(rm, S[nf][2 * j + 1]);
                }
                rm = fmaxf(rm, __shfl_xor_sync(0xffffffffu, rm, 1));
                rm = fmaxf(rm, __shfl_xor_sync(0xffffffffu, rm, 2));
                float mn = fmaxf(mj, rm);
                float alpha = __expf(mj - mn);
                float rs = 0.f;
#pragma unroll
                for (int nf = 0; nf < 8; nf++) {
                    float p0 = __expf(S[nf][2 * j] - mn);
                    float p1 = __expf(S[nf][2 * j + 1] - mn);
                    S[nf][2 * j] = p0; S[nf][2 * j + 1] = p1;
                    rs += p0 + p1;
                }
                rs += __shfl_xor_sync(0xffffffffu, rs, 1);
                rs += __shfl_xor_sync(0xffffffffu, rs, 2);
                lj = lj * alpha + rs;
                mj = mn;
#pragma unroll
                for (int nf = 0; nf < 8; nf++) {
                    O[nf][2 * j] *= alpha;
                    O[nf][2 * j + 1] *= alpha;
                }
            }

#pragma unroll
            for (int ks = 0; ks < 4; ks++) {
                uint32_t ah[4], al[4];
#pragma unroll
                for (int q = 0; q < 4; q++) {
                    int sf = 2 * ks + (q >> 1);
                    int c0 = (q & 1) * 2;
                    float p0 = S[sf][c0], p1 = S[sf][c0 + 1];
                    float h0 = __bfloat162float(__float2bfloat16_rn(p0));
                    float h1 = __bfloat162float(__float2bfloat16_rn(p1));
                    ah[q] = pack_bf2(h0, h1);
                    al[q] = pack_bf2(p0 - h0, p1 - h1);
                }
#pragma unroll
                for (int dp = 0; dp < 4; dp++) {
                    uint32_t va = stg + (uint32_t)(ks * 16 + ((lane >> 3) & 1) * 8 + (lane & 7)) * FROW
                                  + dp * 32 + (lane >> 4) * 16;
                    uint32_t vh[4], vl[4];
                    ldsm4t(vh, va + FVH);
                    ldsm4t(vl, va + FVL);
                    mma16816(O[2 * dp],     ah, &vh[0]);
                    mma16816(O[2 * dp],     al, &vh[0]);
                    mma16816(O[2 * dp],     ah, &vl[0]);
                    mma16816(O[2 * dp + 1], ah, &vh[2]);
                    mma16816(O[2 * dp + 1], al, &vh[2]);
                    mma16816(O[2 * dp + 1], ah, &vl[2]);
                }
            }
        }
        __syncthreads();
        load_kv(kt + 3);
    }

    float inv0 = 1.0f / l0;
    float inv1 = 1.0f / l1;
    int r0 = q0 + wid * 16 + (lane >> 2);
#pragma unroll
    for (int nf = 0; nf < 8; nf++)
#pragma unroll
        for (int j = 0; j < 2; j++) {
            float inv = j ? inv1 : inv0;
            float v0 = O[nf][2 * j] * inv;
            float v1 = O[nf][2 * j + 1] * inv;
            int t = r0 + j * 8;
            int col = h * 64 + nf * 8 + (lane & 3) * 2;
            float h0 = __bfloat162float(__float2bfloat16_rn(v0));
            float h1 = __bfloat162float(__float2bfloat16_rn(v1));
            *(uint32_t*)&Ahi[(size_t)t * DIM_ + col] = pack_bf2(h0, h1);
            *(uint32_t*)&Alo[(size_t)t * DIM_ + col] = pack_bf2(v0 - h0, v1 - h1);
        }
}

// ================= host launch =================
extern "C" void kernel_launch(void* const* d_in, const int* in_sizes, int n_in,
                              void* d_out, int out_size) {
    const int*   positions = (const int*)d_in[0];
    const float* hidden    = (const float*)d_in[1];
    const float* Wqkv      = (const float*)d_in[2];
    const float* bqkv      = (const float*)d_in[3];
    const float* Wout      = (const float*)d_in[4];
    const float* bout      = (const float*)d_in[5];
    const float* tau_alpha = (const float*)d_in[6];
    const float* tau_wq    = (const float*)d_in[7];
    const float* tau_wv    = (const float*)d_in[8];
    float* out = (float*)d_out;

    float *qkv, *tauq, *tauv, *taupart;
    __nv_bfloat16 *Ahi, *Alo, *Whi, *Wlo, *Ghi, *Glo, *Twhi, *Twlo;
    __nv_bfloat16 *Qhi, *Qlo, *Khi, *Klo, *Vhi, *Vlo;
    cudaGetSymbolAddress((void**)&qkv,     g_qkv);
    cudaGetSymbolAddress((void**)&tauq,    g_tauq);
    cudaGetSymbolAddress((void**)&tauv,    g_tauv);
    cudaGetSymbolAddress((void**)&taupart, g_taupart);
    cudaGetSymbolAddress((void**)&Ahi,     g_Ahi);
    cudaGetSymbolAddress((void**)&Alo,     g_Alo);
    cudaGetSymbolAddress((void**)&Whi,     g_Whi);
    cudaGetSymbolAddress((void**)&Wlo,     g_Wlo);
    cudaGetSymbolAddress((void**)&Ghi,     g_Ghi);
    cudaGetSymbolAddress((void**)&Glo,     g_Glo);
    cudaGetSymbolAddress((void**)&Twhi,    g_Twhi);
    cudaGetSymbolAddress((void**)&Twlo,    g_Twlo);
    cudaGetSymbolAddress((void**)&Qhi,     g_Qhi);
    cudaGetSymbolAddress((void**)&Qlo,     g_Qlo);
    cudaGetSymbolAddress((void**)&Khi,     g_Khi);
    cudaGetSymbolAddress((void**)&Klo,     g_Klo);
    cudaGetSymbolAddress((void**)&Vhi,     g_Vhi);
    cudaGetSymbolAddress((void**)&Vlo,     g_Vlo);

    cudaFuncSetAttribute(gemm_hmma_kernel, cudaFuncAttributeMaxDynamicSharedMemorySize, GSMEM);
    cudaFuncSetAttribute(tau_hmma_kernel, cudaFuncAttributeMaxDynamicSharedMemorySize, TSMEM);
    cudaFuncSetAttribute(flash_hmma_kernel, cudaFuncAttributeMaxDynamicSharedMemorySize, FLASH2_SMEM);

    // 1. decompose inputs
    decomp_kernel<<<(T_ * DIM_ / 4 + 255) / 256, 256>>>(hidden, Ahi, Alo, T_ * DIM_ / 4);
    decomp_kernel<<<(QKVD * DIM_ / 4 + 255) / 256, 256>>>(Wqkv, Whi, Wlo, QKVD * DIM_ / 4);
    decomp_kernel<<<(32 * QKVD / 4 + 255) / 256, 256>>>(tau_wq, Twhi, Twlo, 32 * QKVD / 4);
    decomp_kernel<<<(32 * QKVD / 4 + 255) / 256, 256>>>(tau_wv, Twhi + 32 * QKVD, Twlo + 32 * QKVD, 32 * QKVD / 4);
    // 2. qkv = hidden @ Wqkv^T + bqkv, fused gelu+decomp -> Ghi/Glo
    gemm_hmma_kernel<<<dim3(QKVD / 128, T_ / 128), 256, GSMEM>>>(
        Ahi, Alo, Whi, Wlo, bqkv, qkv, Ghi, Glo, QKVD, DIM_);
    // 3. tau projections on tensor cores
    tau_hmma_kernel<<<dim3(T_ / 128, 8), 256, TSMEM>>>(Ghi, Glo, Twhi, Twlo, taupart);
    tau_finish_kernel<<<(T_ * 64 + 255) / 256, 256>>>(taupart, tau_alpha, positions, tauq, tauv);
    // 4. scale + rope -> bf16 hi/lo Q/K/V planes
    prep_kernel<<<T_, 256>>>(qkv, positions, tauq, tauv, Qhi, Qlo, Khi, Klo, Vhi, Vlo);
    // 5. causal flash attention -> attn hi/lo planes
    flash_hmma_kernel<<<dim3(T_ / 128, NH), 256, FLASH2_SMEM>>>(
        Qhi, Qlo, Khi, Klo, Vhi, Vlo, Ahi, Alo);
    // 6. out = attn @ Wout^T + bout
    decomp_kernel<<<(DIM_ * DIM_ / 4 + 255) / 256, 256>>>(Wout, Whi, Wlo, DIM_ * DIM_ / 4);
    gemm_hmma_kernel<<<dim3(DIM_ / 128, T_ / 128), 256, GSMEM>>>(
        Ahi, Alo, Whi, Wlo, bout, out, nullptr, nullptr, DIM_, DIM_);
}